// round 14
// baseline (speedup 1.0000x reference)
#include <cuda_runtime.h>
#include <math.h>

#define HH   256
#define NHH  8
#define CC   100
#define NMAX 262144
#define BY   9            // partial chunks per commit in k_main
#define TW   8            // nodes per shared tile in k_main
#define STAGES 4

typedef unsigned long long ull;

// ---------------- device scratch ----------------
__device__ __align__(16) float g_wqk[NHH * HH];
__device__ int   g_counts[CC];
__device__ int   g_offsets[CC + 1];
__device__ int   g_cursor[CC];
__device__ int   g_sorted[NMAX];
__device__ __align__(16) float g_Apart[CC * BY * NHH * HH];
__device__ float g_denpart[CC * BY * NHH];
__device__ __align__(16) float g_x[CC * HH];
__device__ __align__(16) float g_qkv[CC * 3 * HH];

// ---------------- helpers ----------------
__device__ __forceinline__ ull fma2(ull a, ull b, ull c) {
    ull d;
    asm("fma.rn.f32x2 %0, %1, %2, %3;" : "=l"(d) : "l"(a), "l"(b), "l"(c));
    return d;
}
__device__ __forceinline__ void upk2(ull v, float& lo, float& hi) {
    asm("mov.b64 {%0, %1}, %2;" : "=f"(lo), "=f"(hi) : "l"(v));
}
__device__ __forceinline__ ull pk2(float lo, float hi) {
    ull r; asm("mov.b64 %0, {%1, %2};" : "=l"(r) : "f"(lo), "f"(hi)); return r;
}
__device__ __forceinline__ float gelu_exact(float v) {
    return 0.5f * v * (1.0f + erff(v * 0.70710678118654752f));
}
__device__ __forceinline__ void cpasync16(unsigned int saddr, const void* gptr) {
    asm volatile("cp.async.cg.shared.global [%0], [%1], 16;\n" :: "r"(saddr), "l"(gptr));
}
#define CP_COMMIT asm volatile("cp.async.commit_group;\n" ::: "memory")
#define CP_WAIT3  asm volatile("cp.async.wait_group 3;\n" ::: "memory")

__device__ __forceinline__ float block_ln_256(float v, float gg, float bb, float* red) {
    int t = threadIdx.x, lane = t & 31, w = t >> 5;
    float s = v, q = v * v;
#pragma unroll
    for (int off = 16; off > 0; off >>= 1) {
        s += __shfl_xor_sync(0xffffffffu, s, off);
        q += __shfl_xor_sync(0xffffffffu, q, off);
    }
    if (lane == 0) { red[w] = s; red[8 + w] = q; }
    __syncthreads();
    float S = 0.f, Q = 0.f;
#pragma unroll
    for (int i = 0; i < 8; i++) { S += red[i]; Q += red[8 + i]; }
    float mu  = S * (1.0f / 256.0f);
    float var = Q * (1.0f / 256.0f) - mu * mu;
    return (v - mu) * rsqrtf(var + 1e-5f) * gg + bb;
}

// ---------------- setup ----------------
__global__ void k_wqk_init(const float* __restrict__ q, const float* __restrict__ kw) {
    if (blockIdx.x == 8) {
        int t = threadIdx.x;
        if (t < CC) { g_counts[t] = 0; g_cursor[t] = 0; }
        return;
    }
    const float scale = 0.17677669529663687f;
    int h = blockIdx.x, i = threadIdx.x;
    float acc = 0.f;
#pragma unroll 8
    for (int d = 0; d < 32; d++) acc += q[h * 32 + d] * kw[(h * 32 + d) * HH + i];
    g_wqk[h * HH + i] = acc * scale;
}

__global__ void __launch_bounds__(256) k_hist(const int* __restrict__ ci, int n) {
    __shared__ int sh[8][CC];
    int t = threadIdx.x, warp = t >> 5;
    for (int j = t; j < 8 * CC; j += 256) sh[j / CC][j % CC] = 0;
    __syncthreads();
    int n4 = n >> 2;
    const int4* ci4 = (const int4*)ci;
    for (int i = blockIdx.x * 256 + t; i < n4; i += gridDim.x * 256) {
        int4 v = ci4[i];
        atomicAdd(&sh[warp][v.x], 1);
        atomicAdd(&sh[warp][v.y], 1);
        atomicAdd(&sh[warp][v.z], 1);
        atomicAdd(&sh[warp][v.w], 1);
    }
    __syncthreads();
    for (int c = t; c < CC; c += 256) {
        int s = 0;
#pragma unroll
        for (int w = 0; w < 8; w++) s += sh[w][c];
        atomicAdd(&g_counts[c], s);
    }
}

__global__ void __launch_bounds__(256) k_scatter(const int* __restrict__ ci, int n) {
    __shared__ int soff[CC + 1], scnt[CC], sbase[CC], scur[CC];
    int t = threadIdx.x;
    for (int j = t; j < CC; j += 256) { scnt[j] = 0; scur[j] = 0; }
    __syncthreads();
    int per = ((n + gridDim.x - 1) / gridDim.x + 3) & ~3;
    int lo = blockIdx.x * per;
    int hi = min(n, lo + per);
    const int4* ci4 = (const int4*)ci;
    for (int i4 = (lo >> 2) + t; i4 < (hi >> 2); i4 += 256) {
        int4 v = ci4[i4];
        atomicAdd(&scnt[v.x], 1);
        atomicAdd(&scnt[v.y], 1);
        atomicAdd(&scnt[v.z], 1);
        atomicAdd(&scnt[v.w], 1);
    }
    __syncthreads();
    if (t == 0) {
        int s = 0;
        for (int c = 0; c < CC; c++) { soff[c] = s; s += g_counts[c]; }
        soff[CC] = s;
        if (blockIdx.x == 0)
            for (int c = 0; c <= CC; c++) g_offsets[c] = soff[c];
    }
    __syncthreads();
    if (t < CC) sbase[t] = soff[t] + atomicAdd(&g_cursor[t], scnt[t]);
    __syncthreads();
    for (int i = lo + t; i < hi; i += 256) {
        int c = ci[i];
        int p = sbase[c] + atomicAdd(&scur[c], 1);
        g_sorted[p] = i;
    }
}

// ---------------- main streaming pass (cp.async 4-stage pipeline) ----------------
__global__ void __launch_bounds__(128) k_main(const float* __restrict__ X) {
    __shared__ __align__(16) float tile[STAGES][TW * 256];   // 32KB
    int c = blockIdx.x;
    int t = threadIdx.x;
    int warp = t >> 5, lane = t & 31;
    int start = g_offsets[c], end = g_offsets[c + 1];
    int cnt = end - start;
    int chunk = (cnt + BY - 1) / BY;
    int mylo = start + blockIdx.y * chunk;
    int myhi = min(end, mylo + chunk);
    int nt = myhi - mylo;
    if (nt < 0) nt = 0;
    int ntiles = (nt + TW - 1) / TW;

    int h0 = warp * 2;
    ull w2[2][4];
#pragma unroll
    for (int hh = 0; hh < 2; hh++)
#pragma unroll
        for (int k = 0; k < 4; k++)
            w2[hh][k] = *(const ull*)(g_wqk + (h0 + hh) * 256 + k * 64 + 2 * lane);
    ull a2[2][4];
#pragma unroll
    for (int hh = 0; hh < 2; hh++)
#pragma unroll
        for (int k = 0; k < 4; k++) a2[hh][k] = 0ull;
    float dacc[2] = {0.f, 0.f};

    int lr = t >> 4, sub = t & 15;   // 16 threads per row
    unsigned int sbase = (unsigned int)__cvta_generic_to_shared(&tile[0][0])
                       + lr * 1024 + sub * 16;

    if (nt > 0) {
        int safe = g_sorted[mylo];
        // preload + issue stages 0..2
#pragma unroll
        for (int s = 0; s < STAGES - 1; s++) {
            int p = mylo + s * TW + lr;
            int idx = (p < myhi) ? g_sorted[p] : safe;
            if (s < ntiles) {
                unsigned int dst = sbase + s * (TW * 1024);
                const char* src = (const char*)(X + (size_t)idx * 256) + sub * 16;
                cpasync16(dst,        src);
                cpasync16(dst + 256,  src + 256);
                cpasync16(dst + 512,  src + 512);
                cpasync16(dst + 768,  src + 768);
            }
            CP_COMMIT;
        }
        int pn = mylo + 3 * TW + lr;
        int inxt = (pn < myhi) ? g_sorted[pn] : safe;

        for (int j = 0; j < ntiles; j++) {
            __syncthreads();                    // all warps done with buffer (j+3)&3
            if (j + 3 < ntiles) {
                unsigned int dst = sbase + ((j + 3) & (STAGES - 1)) * (TW * 1024);
                const char* src = (const char*)(X + (size_t)inxt * 256) + sub * 16;
                cpasync16(dst,        src);
                cpasync16(dst + 256,  src + 256);
                cpasync16(dst + 512,  src + 512);
                cpasync16(dst + 768,  src + 768);
            }
            CP_COMMIT;
            {
                int p = mylo + (j + 4) * TW + lr;
                inxt = (p < myhi) ? g_sorted[p] : safe;
            }
            CP_WAIT3;
            __syncthreads();                    // tile j visible to all warps

            int rmax = min(TW, nt - j * TW);
            const float* tb = tile[j & (STAGES - 1)];
            for (int rr = 0; rr < rmax; rr++) {
                const float* row = tb + rr * 256;
                ull x0 = *(const ull*)(row + 2 * lane);
                ull x1 = *(const ull*)(row + 64 + 2 * lane);
                ull x2 = *(const ull*)(row + 128 + 2 * lane);
                ull x3 = *(const ull*)(row + 192 + 2 * lane);
                float p0, p1;
                {
                    ull acc = fma2(x0, w2[0][0], 0ull);
                    acc = fma2(x1, w2[0][1], acc);
                    acc = fma2(x2, w2[0][2], acc);
                    acc = fma2(x3, w2[0][3], acc);
                    float lo, hi; upk2(acc, lo, hi); p0 = lo + hi;
                }
                {
                    ull acc = fma2(x0, w2[1][0], 0ull);
                    acc = fma2(x1, w2[1][1], acc);
                    acc = fma2(x2, w2[1][2], acc);
                    acc = fma2(x3, w2[1][3], acc);
                    float lo, hi; upk2(acc, lo, hi); p1 = lo + hi;
                }
#pragma unroll
                for (int off = 16; off > 0; off >>= 1) {
                    p0 += __shfl_xor_sync(0xffffffffu, p0, off);
                    p1 += __shfl_xor_sync(0xffffffffu, p1, off);
                }
                float e0 = __expf(p0), e1 = __expf(p1);
                dacc[0] += e0; dacc[1] += e1;
                ull e02 = pk2(e0, e0), e12 = pk2(e1, e1);
                a2[0][0] = fma2(e02, x0, a2[0][0]);
                a2[0][1] = fma2(e02, x1, a2[0][1]);
                a2[0][2] = fma2(e02, x2, a2[0][2]);
                a2[0][3] = fma2(e02, x3, a2[0][3]);
                a2[1][0] = fma2(e12, x0, a2[1][0]);
                a2[1][1] = fma2(e12, x1, a2[1][1]);
                a2[1][2] = fma2(e12, x2, a2[1][2]);
                a2[1][3] = fma2(e12, x3, a2[1][3]);
            }
        }
    }
    ull* base = (ull*)(g_Apart + (size_t)(c * BY + blockIdx.y) * 2048);
#pragma unroll
    for (int hh = 0; hh < 2; hh++)
#pragma unroll
        for (int k = 0; k < 4; k++)
            base[(h0 + hh) * 128 + k * 32 + lane] = a2[hh][k];
    if (lane == 0) {
        g_denpart[(c * BY + blockIdx.y) * 8 + h0]     = dacc[0];
        g_denpart[(c * BY + blockIdx.y) * 8 + h0 + 1] = dacc[1];
    }
}

// ---------------- pooling epilogue ----------------
__global__ void __launch_bounds__(256) k_pool(const float* __restrict__ vw,
                                              const float* __restrict__ vb,
                                              const float* __restrict__ pw,
                                              const float* __restrict__ pb,
                                              const float* __restrict__ png,
                                              const float* __restrict__ pnb) {
    int c = blockIdx.x, t = threadIdx.x, warp = t >> 5, lane = t & 31;
    __shared__ __align__(16) float shA[2048];
    __shared__ __align__(16) float shP[256];
    __shared__ float shO[256];
    __shared__ float shden[8];
    __shared__ float red[16];
#pragma unroll
    for (int j = 0; j < 8; j++) {
        float s = 0.f;
#pragma unroll
        for (int p = 0; p < BY; p++)
            s += g_Apart[(size_t)(c * BY + p) * 2048 + t + 256 * j];
        shA[t + 256 * j] = s;
    }
    if (t < 8) {
        float d = 0.f;
#pragma unroll
        for (int p = 0; p < BY; p++) d += g_denpart[(c * BY + p) * 8 + t];
        shden[t] = d;
    }
    __syncthreads();
    int h = warp;
    float den = shden[h];
    float rden = den > 0.f ? 1.f / den : 0.f;
    for (int d = 0; d < 32; d++) {
        const float* w = vw + (h * 32 + d) * 256;
        float4 wa = *(const float4*)(w + 4 * lane);
        float4 wb = *(const float4*)(w + 128 + 4 * lane);
        float4 xa = *(const float4*)(shA + h * 256 + 4 * lane);
        float4 xb = *(const float4*)(shA + h * 256 + 128 + 4 * lane);
        float s = wa.x * xa.x + wa.y * xa.y + wa.z * xa.z + wa.w * xa.w
                + wb.x * xb.x + wb.y * xb.y + wb.z * xb.z + wb.w * xb.w;
#pragma unroll
        for (int off = 16; off > 0; off >>= 1) s += __shfl_xor_sync(0xffffffffu, s, off);
        if (lane == 0)
            shP[h * 32 + d] = (den > 0.f) ? (s * rden + vb[h * 32 + d]) : 0.f;
    }
    __syncthreads();
    for (int d = 0; d < 32; d++) {
        int j = warp * 32 + d;
        const float* w = pw + j * 256;
        float4 wa = *(const float4*)(w + 4 * lane);
        float4 wb = *(const float4*)(w + 128 + 4 * lane);
        float4 xa = *(const float4*)(shP + 4 * lane);
        float4 xb = *(const float4*)(shP + 128 + 4 * lane);
        float s = wa.x * xa.x + wa.y * xa.y + wa.z * xa.z + wa.w * xa.w
                + wb.x * xb.x + wb.y * xb.y + wb.z * xb.z + wb.w * xb.w;
#pragma unroll
        for (int off = 16; off > 0; off >>= 1) s += __shfl_xor_sync(0xffffffffu, s, off);
        if (lane == 0) shO[j] = s + pb[j];
    }
    __syncthreads();
    float r = block_ln_256(shO[t], png[t], pnb[t], red);
    g_x[c * 256 + t] = (g_counts[c] > 0) ? r : 0.f;
}

// qkv projection: 4 commits per block, 128-row slice per blockIdx.y (6 slices).
__global__ void __launch_bounds__(256) k_qkv(const float* __restrict__ W,
                                             const float* __restrict__ B) {
    int cbase = blockIdx.x * 4, t = threadIdx.x, warp = t >> 5, lane = t & 31;
    int jbase = blockIdx.y * 128;
    __shared__ __align__(16) float shx[4][256];
#pragma unroll
    for (int cc = 0; cc < 4; cc++)
        shx[cc][t] = g_x[(cbase + cc) * 256 + t];
    __syncthreads();
    for (int r = 0; r < 16; r++) {
        int j = jbase + warp * 16 + r;
        const float* w = W + (size_t)j * 256;
        float4 wa = *(const float4*)(w + 4 * lane);
        float4 wb = *(const float4*)(w + 128 + 4 * lane);
        float s[4];
#pragma unroll
        for (int cc = 0; cc < 4; cc++) {
            float4 xa = *(const float4*)(&shx[cc][4 * lane]);
            float4 xb = *(const float4*)(&shx[cc][128 + 4 * lane]);
            s[cc] = wa.x * xa.x + wa.y * xa.y + wa.z * xa.z + wa.w * xa.w
                  + wb.x * xb.x + wb.y * xb.y + wb.z * xb.z + wb.w * xb.w;
        }
#pragma unroll
        for (int off = 16; off > 0; off >>= 1)
#pragma unroll
            for (int cc = 0; cc < 4; cc++)
                s[cc] += __shfl_xor_sync(0xffffffffu, s[cc], off);
        if (lane == 0) {
            float bj = B[j];
#pragma unroll
            for (int cc = 0; cc < 4; cc++)
                g_qkv[(cbase + cc) * 768 + j] = s[cc] + bj;
        }
    }
}

// ---------------- fused per-commit layer: attn + outproj + LN1 + ff1 + ff2 + LN2 (+head) ----------------
__global__ void __launch_bounds__(256) k_layer(
    const float* __restrict__ Wo, const float* __restrict__ Bo,
    const float* __restrict__ g1, const float* __restrict__ b1,
    const float* __restrict__ W1, const float* __restrict__ B1,
    const float* __restrict__ W2, const float* __restrict__ B2,
    const float* __restrict__ g2, const float* __restrict__ b2,
    int final_layer,
    const float* __restrict__ r1w, const float* __restrict__ r1b,
    const float* __restrict__ r2w, const float* __restrict__ r2b,
    float* __restrict__ out) {
    int c = blockIdx.x, t = threadIdx.x, h = t >> 5, lane = t & 31;
    __shared__ __align__(16) float shq[256];
    __shared__ float she[8][128];
    __shared__ __align__(16) float satt[256];
    __shared__ float sho[256];
    __shared__ __align__(16) float shx[256];
    __shared__ __align__(16) float shff[1024];
    __shared__ float shh[128];
    __shared__ float red[16];

    shq[t] = g_qkv[c * 768 + t];
    __syncthreads();

    // ---- attention (warp h owns head h) ----
    const float scale = 0.17677669529663687f;
    float sc[4];
#pragma unroll
    for (int r = 0; r < 4; r++) {
        int m = lane + 32 * r;
        if (m < CC) {
            const float* kk = g_qkv + m * 768 + 256 + h * 32;
            const float* qq = shq + h * 32;
            float s = 0.f;
#pragma unroll
            for (int kx = 0; kx < 8; kx++) {
                float4 a = *(const float4*)(kk + 4 * kx);
                float4 b = *(const float4*)(qq + 4 * kx);
                s += a.x * b.x + a.y * b.y + a.z * b.z + a.w * b.w;
            }
            sc[r] = s * scale;
        } else sc[r] = -3.0e38f;
    }
    float M = fmaxf(fmaxf(sc[0], sc[1]), fmaxf(sc[2], sc[3]));
#pragma unroll
    for (int off = 16; off > 0; off >>= 1) M = fmaxf(M, __shfl_xor_sync(0xffffffffu, M, off));
    float sum = 0.f;
#pragma unroll
    for (int r = 0; r < 4; r++) {
        int m = lane + 32 * r;
        float e = (m < CC) ? __expf(sc[r] - M) : 0.f;
        if (m < CC) she[h][m] = e;
        sum += e;
    }
#pragma unroll
    for (int off = 16; off > 0; off >>= 1) sum += __shfl_xor_sync(0xffffffffu, sum, off);
    __syncwarp();
    float inv = 1.f / sum;
    float acc = 0.f;
#pragma unroll 4
    for (int m = 0; m < CC; m++)
        acc += she[h][m] * g_qkv[m * 768 + 512 + h * 32 + lane];
    satt[h * 32 + lane] = acc * inv;
    __syncthreads();

    // ---- output projection ----
    for (int d = 0; d < 32; d++) {
        int j = h * 32 + d;
        const float* w = Wo + (size_t)j * 256;
        float4 wa = *(const float4*)(w + 4 * lane);
        float4 wb = *(const float4*)(w + 128 + 4 * lane);
        float4 xa = *(const float4*)(satt + 4 * lane);
        float4 xb = *(const float4*)(satt + 128 + 4 * lane);
        float s = wa.x * xa.x + wa.y * xa.y + wa.z * xa.z + wa.w * xa.w
                + wb.x * xb.x + wb.y * xb.y + wb.z * xb.z + wb.w * xb.w;
#pragma unroll
        for (int off = 16; off > 0; off >>= 1) s += __shfl_xor_sync(0xffffffffu, s, off);
        if (lane == 0) sho[j] = s;
    }
    __syncthreads();

    // ---- residual + LN1 ----
    {
        float v = g_x[c * 256 + t] + sho[t] + Bo[t];
        float r = block_ln_256(v, g1[t], b1[t], red);
        shx[t] = r;
    }
    __syncthreads();

    // ---- ff1 + gelu (1024 rows, 8 warps x 128) ----
    for (int r = 0; r < 128; r++) {
        int j = h * 128 + r;
        const float* w = W1 + (size_t)j * 256;
        float4 wa = *(const float4*)(w + 4 * lane);
        float4 wb = *(const float4*)(w + 128 + 4 * lane);
        float4 xa = *(const float4*)(&shx[4 * lane]);
        float4 xb = *(const float4*)(&shx[128 + 4 * lane]);
        float s = wa.x * xa.x + wa.y * xa.y + wa.z * xa.z + wa.w * xa.w
                + wb.x * xb.x + wb.y * xb.y + wb.z * xb.z + wb.w * xb.w;
#pragma unroll
        for (int off = 16; off > 0; off >>= 1) s += __shfl_xor_sync(0xffffffffu, s, off);
        if (lane == 0) shff[j] = gelu_exact(s + B1[j]);
    }
    __syncthreads();

    // ---- ff2 (256 rows, K=1024) ----
    for (int r = 0; r < 32; r++) {
        int j = h * 32 + r;
        const float4* wr = (const float4*)(W2 + (size_t)j * 1024);
        float a2 = 0.f;
#pragma unroll
        for (int q8 = 0; q8 < 8; q8++) {
            float4 wv = wr[q8 * 32 + lane];
            float4 x = *(const float4*)(&shff[q8 * 128 + 4 * lane]);
            a2 += wv.x * x.x + wv.y * x.y + wv.z * x.z + wv.w * x.w;
        }
#pragma unroll
        for (int off = 16; off > 0; off >>= 1) a2 += __shfl_xor_sync(0xffffffffu, a2, off);
        if (lane == 0) sho[j] = a2 + B2[j];
    }
    __syncthreads();

    // ---- residual + LN2 (residual = post-LN1 shx) ----
    float v = shx[t] + sho[t];
    float r2v = block_ln_256(v, g2[t], b2[t], red);
    if (!final_layer) { g_x[c * 256 + t] = r2v; return; }
    __syncthreads();
    shq[t] = r2v;          // reuse shq as final x
    __syncthreads();

    // ---- ranking head ----
    for (int rr = 0; rr < 16; rr++) {
        int j = h * 16 + rr;
        const float* w = r1w + (size_t)j * 256;
        float4 wa = *(const float4*)(w + 4 * lane);
        float4 wb = *(const float4*)(w + 128 + 4 * lane);
        float4 xa = *(const float4*)(&shq[4 * lane]);
        float4 xb = *(const float4*)(&shq[128 + 4 * lane]);
        float s = wa.x * xa.x + wa.y * xa.y + wa.z * xa.z + wa.w * xa.w
                + wb.x * xb.x + wb.y * xb.y + wb.z * xb.z + wb.w * xb.w;
#pragma unroll
        for (int off = 16; off > 0; off >>= 1) s += __shfl_xor_sync(0xffffffffu, s, off);
        if (lane == 0) shh[j] = gelu_exact(s + r1b[j]);
    }
    __syncthreads();
    if (h == 0) {
        float s = 0.f;
#pragma unroll
        for (int rr = 0; rr < 4; rr++)
            s += shh[lane + 32 * rr] * r2w[lane + 32 * rr];
#pragma unroll
        for (int off = 16; off > 0; off >>= 1) s += __shfl_xor_sync(0xffffffffu, s, off);
        if (lane == 0) out[c] = s + r2b[0];
    }
}

// ---------------- launch ----------------
extern "C" void kernel_launch(void* const* d_in, const int* in_sizes, int n_in,
                              void* d_out, int out_size) {
    const float* x    = (const float*)d_in[0];
    const int*   ci   = (const int*)d_in[1];
    const float* q    = (const float*)d_in[3];
    const float* kw   = (const float*)d_in[4];
    const float* vw   = (const float*)d_in[6];
    const float* vb   = (const float*)d_in[7];
    const float* pw   = (const float*)d_in[8];
    const float* pb   = (const float*)d_in[9];
    const float* png  = (const float*)d_in[10];
    const float* pnb  = (const float*)d_in[11];
    const float* tinw = (const float*)d_in[12];
    const float* tinb = (const float*)d_in[13];
    const float* totw = (const float*)d_in[14];
    const float* totb = (const float*)d_in[15];
    const float* ln1g = (const float*)d_in[16];
    const float* ln1b = (const float*)d_in[17];
    const float* ff1w = (const float*)d_in[18];
    const float* ff1b = (const float*)d_in[19];
    const float* ff2w = (const float*)d_in[20];
    const float* ff2b = (const float*)d_in[21];
    const float* ln2g = (const float*)d_in[22];
    const float* ln2b = (const float*)d_in[23];
    const float* r1w  = (const float*)d_in[24];
    const float* r1b  = (const float*)d_in[25];
    const float* r2w  = (const float*)d_in[26];
    const float* r2b  = (const float*)d_in[27];
    float* out = (float*)d_out;
    int n = in_sizes[0] / HH;

    k_wqk_init<<<9, 256>>>(q, kw);            // launch 1
    k_hist<<<256, 256>>>(ci, n);              // launch 2
    k_scatter<<<256, 256>>>(ci, n);           // launch 3
    k_main<<<dim3(CC, BY), 128>>>(x);         // launch 4  (profiled)
    k_pool<<<CC, 256>>>(vw, vb, pw, pb, png, pnb);
    for (int l = 0; l < 2; l++) {
        k_qkv<<<dim3(25, 6), 256>>>(tinw + (size_t)l * 768 * 256, tinb + l * 768);
        k_layer<<<CC, 256>>>(totw + (size_t)l * 256 * 256, totb + l * 256,
                             ln1g + l * 256, ln1b + l * 256,
                             ff1w + (size_t)l * 1024 * 256, ff1b + l * 1024,
                             ff2w + (size_t)l * 256 * 1024, ff2b + l * 256,
                             ln2g + l * 256, ln2b + l * 256,
                             (l == 1) ? 1 : 0, r1w, r1b, r2w, r2b, out);
    }
}

// round 15
// speedup vs baseline: 1.3798x; 1.3798x over previous
#include <cuda_runtime.h>
#include <math.h>

#define HH   256
#define NHH  8
#define CC   100
#define NMAX 262144
#define BY   18           // partial chunks per commit in k_main
#define TW   16           // nodes per shared tile in k_main (was 8)

typedef unsigned long long ull;

// ---------------- device scratch ----------------
__device__ __align__(16) float g_wqk[NHH * HH];
__device__ int   g_counts[CC];
__device__ int   g_offsets[CC + 1];
__device__ int   g_cursor[CC];
__device__ int   g_sorted[NMAX];
__device__ __align__(16) float g_Apart[CC * BY * NHH * HH];   // ~14.7MB partials
__device__ float g_denpart[CC * BY * NHH];
__device__ __align__(16) float g_x[CC * HH];
__device__ __align__(16) float g_qkv[CC * 3 * HH];
__device__ __align__(16) float g_ff[CC * 4 * HH];

// ---------------- helpers ----------------
__device__ __forceinline__ ull fma2(ull a, ull b, ull c) {
    ull d;
    asm("fma.rn.f32x2 %0, %1, %2, %3;" : "=l"(d) : "l"(a), "l"(b), "l"(c));
    return d;
}
__device__ __forceinline__ void upk2(ull v, float& lo, float& hi) {
    asm("mov.b64 {%0, %1}, %2;" : "=f"(lo), "=f"(hi) : "l"(v));
}
__device__ __forceinline__ ull pk2(float lo, float hi) {
    ull r; asm("mov.b64 %0, {%1, %2};" : "=l"(r) : "f"(lo), "f"(hi)); return r;
}
__device__ __forceinline__ float gelu_exact(float v) {
    return 0.5f * v * (1.0f + erff(v * 0.70710678118654752f));
}

__device__ __forceinline__ float block_ln_256(float v, float gg, float bb, float* red) {
    int t = threadIdx.x, lane = t & 31, w = t >> 5;
    float s = v, q = v * v;
#pragma unroll
    for (int off = 16; off > 0; off >>= 1) {
        s += __shfl_xor_sync(0xffffffffu, s, off);
        q += __shfl_xor_sync(0xffffffffu, q, off);
    }
    if (lane == 0) { red[w] = s; red[8 + w] = q; }
    __syncthreads();
    float S = 0.f, Q = 0.f;
#pragma unroll
    for (int i = 0; i < 8; i++) { S += red[i]; Q += red[8 + i]; }
    float mu  = S * (1.0f / 256.0f);
    float var = Q * (1.0f / 256.0f) - mu * mu;
    return (v - mu) * rsqrtf(var + 1e-5f) * gg + bb;
}

// ---------------- setup ----------------
__global__ void k_wqk_init(const float* __restrict__ q, const float* __restrict__ kw) {
    if (blockIdx.x == 8) {
        int t = threadIdx.x;
        if (t < CC) { g_counts[t] = 0; g_cursor[t] = 0; }
        return;
    }
    const float scale = 0.17677669529663687f;
    int h = blockIdx.x, i = threadIdx.x;
    float acc = 0.f;
#pragma unroll 8
    for (int d = 0; d < 32; d++) acc += q[h * 32 + d] * kw[(h * 32 + d) * HH + i];
    g_wqk[h * HH + i] = acc * scale;
}

__global__ void __launch_bounds__(256) k_hist(const int* __restrict__ ci, int n) {
    __shared__ int sh[8][CC];
    int t = threadIdx.x, warp = t >> 5;
    for (int j = t; j < 8 * CC; j += 256) sh[j / CC][j % CC] = 0;
    __syncthreads();
    int n4 = n >> 2;
    const int4* ci4 = (const int4*)ci;
    for (int i = blockIdx.x * 256 + t; i < n4; i += gridDim.x * 256) {
        int4 v = ci4[i];
        atomicAdd(&sh[warp][v.x], 1);
        atomicAdd(&sh[warp][v.y], 1);
        atomicAdd(&sh[warp][v.z], 1);
        atomicAdd(&sh[warp][v.w], 1);
    }
    __syncthreads();
    for (int c = t; c < CC; c += 256) {
        int s = 0;
#pragma unroll
        for (int w = 0; w < 8; w++) s += sh[w][c];
        atomicAdd(&g_counts[c], s);
    }
}

__global__ void __launch_bounds__(256) k_scatter(const int* __restrict__ ci, int n) {
    __shared__ int soff[CC + 1], scnt[CC], sbase[CC], scur[CC];
    int t = threadIdx.x;
    for (int j = t; j < CC; j += 256) { scnt[j] = 0; scur[j] = 0; }
    __syncthreads();
    int per = ((n + gridDim.x - 1) / gridDim.x + 3) & ~3;
    int lo = blockIdx.x * per;
    int hi = min(n, lo + per);
    const int4* ci4 = (const int4*)ci;
    for (int i4 = (lo >> 2) + t; i4 < (hi >> 2); i4 += 256) {
        int4 v = ci4[i4];
        atomicAdd(&scnt[v.x], 1);
        atomicAdd(&scnt[v.y], 1);
        atomicAdd(&scnt[v.z], 1);
        atomicAdd(&scnt[v.w], 1);
    }
    __syncthreads();
    if (t == 0) {
        int s = 0;
        for (int c = 0; c < CC; c++) { soff[c] = s; s += g_counts[c]; }
        soff[CC] = s;
        if (blockIdx.x == 0)
            for (int c = 0; c <= CC; c++) g_offsets[c] = soff[c];
    }
    __syncthreads();
    if (t < CC) sbase[t] = soff[t] + atomicAdd(&g_cursor[t], scnt[t]);
    __syncthreads();
    for (int i = lo + t; i < hi; i += 256) {
        int c = ci[i];
        int p = sbase[c] + atomicAdd(&scur[c], 1);
        g_sorted[p] = i;
    }
}

// ---------------- main streaming pass ----------------
// CTA = 128 threads (4 warps). Warp w owns heads {2w, 2w+1}. Tiles of TW=16 rows
// staged in shared (double buffered): each thread loads 2 rows x 4 float4s.
__global__ void __launch_bounds__(128) k_main(const float* __restrict__ X) {
    __shared__ __align__(16) float tile[2][TW * 256];   // 32KB
    int c = blockIdx.x;
    int t = threadIdx.x;
    int warp = t >> 5, lane = t & 31;
    int start = g_offsets[c], end = g_offsets[c + 1];
    int cnt = end - start;
    int chunk = (cnt + BY - 1) / BY;
    int mylo = start + blockIdx.y * chunk;
    int myhi = min(end, mylo + chunk);
    int nt = myhi - mylo;
    int ntiles = (nt + TW - 1) / TW;

    int h0 = warp * 2;
    ull w2[2][4];
#pragma unroll
    for (int hh = 0; hh < 2; hh++)
#pragma unroll
        for (int k = 0; k < 4; k++)
            w2[hh][k] = *(const ull*)(g_wqk + (h0 + hh) * 256 + k * 64 + 2 * lane);
    ull a2[2][4];
#pragma unroll
    for (int hh = 0; hh < 2; hh++)
#pragma unroll
        for (int k = 0; k < 4; k++) a2[hh][k] = 0ull;
    float dacc[2] = {0.f, 0.f};

    int lr = t >> 4, sub = t & 15;   // 16 threads per row; rows lr and lr+8

    if (nt > 0) {
        // load tile 0
#pragma unroll
        for (int r2 = 0; r2 < 2; r2++) {
            int row = lr + 8 * r2;
            int p = mylo + row;
            int node = (p < myhi) ? g_sorted[p] : g_sorted[mylo];
            const float4* src = (const float4*)(X + (size_t)node * 256);
            float4* dst = (float4*)(&tile[0][row * 256]);
            dst[sub]      = __ldcs(src + sub);
            dst[sub + 16] = __ldcs(src + sub + 16);
            dst[sub + 32] = __ldcs(src + sub + 32);
            dst[sub + 48] = __ldcs(src + sub + 48);
        }
        int buf = 0;
        for (int j = 0; j < ntiles; j++) {
            __syncthreads();
            if (j + 1 < ntiles) {
#pragma unroll
                for (int r2 = 0; r2 < 2; r2++) {
                    int row = lr + 8 * r2;
                    int p = mylo + (j + 1) * TW + row;
                    int node = (p < myhi) ? g_sorted[p] : g_sorted[mylo];
                    const float4* src = (const float4*)(X + (size_t)node * 256);
                    float4* dst = (float4*)(&tile[buf ^ 1][row * 256]);
                    dst[sub]      = __ldcs(src + sub);
                    dst[sub + 16] = __ldcs(src + sub + 16);
                    dst[sub + 32] = __ldcs(src + sub + 32);
                    dst[sub + 48] = __ldcs(src + sub + 48);
                }
            }
            int rmax = min(TW, nt - j * TW);
            const float* tb = tile[buf];
            for (int rr = 0; rr < rmax; rr++) {
                const float* row = tb + rr * 256;
                ull x0 = *(const ull*)(row + 2 * lane);
                ull x1 = *(const ull*)(row + 64 + 2 * lane);
                ull x2 = *(const ull*)(row + 128 + 2 * lane);
                ull x3 = *(const ull*)(row + 192 + 2 * lane);
                float p0, p1;
                {
                    ull acc = fma2(x0, w2[0][0], 0ull);
                    acc = fma2(x1, w2[0][1], acc);
                    acc = fma2(x2, w2[0][2], acc);
                    acc = fma2(x3, w2[0][3], acc);
                    float lo, hi; upk2(acc, lo, hi); p0 = lo + hi;
                }
                {
                    ull acc = fma2(x0, w2[1][0], 0ull);
                    acc = fma2(x1, w2[1][1], acc);
                    acc = fma2(x2, w2[1][2], acc);
                    acc = fma2(x3, w2[1][3], acc);
                    float lo, hi; upk2(acc, lo, hi); p1 = lo + hi;
                }
#pragma unroll
                for (int off = 16; off > 0; off >>= 1) {
                    p0 += __shfl_xor_sync(0xffffffffu, p0, off);
                    p1 += __shfl_xor_sync(0xffffffffu, p1, off);
                }
                float e0 = __expf(p0), e1 = __expf(p1);
                dacc[0] += e0; dacc[1] += e1;
                ull e02 = pk2(e0, e0), e12 = pk2(e1, e1);
                a2[0][0] = fma2(e02, x0, a2[0][0]);
                a2[0][1] = fma2(e02, x1, a2[0][1]);
                a2[0][2] = fma2(e02, x2, a2[0][2]);
                a2[0][3] = fma2(e02, x3, a2[0][3]);
                a2[1][0] = fma2(e12, x0, a2[1][0]);
                a2[1][1] = fma2(e12, x1, a2[1][1]);
                a2[1][2] = fma2(e12, x2, a2[1][2]);
                a2[1][3] = fma2(e12, x3, a2[1][3]);
            }
            buf ^= 1;
        }
    }
    ull* base = (ull*)(g_Apart + (size_t)(c * BY + blockIdx.y) * 2048);
#pragma unroll
    for (int hh = 0; hh < 2; hh++)
#pragma unroll
        for (int k = 0; k < 4; k++)
            base[(h0 + hh) * 128 + k * 32 + lane] = a2[hh][k];
    if (lane == 0) {
        g_denpart[(c * BY + blockIdx.y) * 8 + h0]     = dacc[0];
        g_denpart[(c * BY + blockIdx.y) * 8 + h0 + 1] = dacc[1];
    }
}

// ---------------- pooling epilogue ----------------
__global__ void __launch_bounds__(256) k_pool(const float* __restrict__ vw,
                                              const float* __restrict__ vb,
                                              const float* __restrict__ pw,
                                              const float* __restrict__ pb,
                                              const float* __restrict__ png,
                                              const float* __restrict__ pnb) {
    int c = blockIdx.x, t = threadIdx.x, warp = t >> 5, lane = t & 31;
    __shared__ __align__(16) float shA[2048];
    __shared__ __align__(16) float shP[256];
    __shared__ float shO[256];
    __shared__ float shden[8];
    __shared__ float red[16];
#pragma unroll
    for (int j = 0; j < 8; j++) {
        float s = 0.f;
#pragma unroll
        for (int p = 0; p < BY; p++)
            s += g_Apart[(size_t)(c * BY + p) * 2048 + t + 256 * j];
        shA[t + 256 * j] = s;
    }
    if (t < 8) {
        float d = 0.f;
#pragma unroll
        for (int p = 0; p < BY; p++) d += g_denpart[(c * BY + p) * 8 + t];
        shden[t] = d;
    }
    __syncthreads();
    int h = warp;
    float den = shden[h];
    float rden = den > 0.f ? 1.f / den : 0.f;
    for (int d = 0; d < 32; d++) {
        const float* w = vw + (h * 32 + d) * 256;
        float4 wa = *(const float4*)(w + 4 * lane);
        float4 wb = *(const float4*)(w + 128 + 4 * lane);
        float4 xa = *(const float4*)(shA + h * 256 + 4 * lane);
        float4 xb = *(const float4*)(shA + h * 256 + 128 + 4 * lane);
        float s = wa.x * xa.x + wa.y * xa.y + wa.z * xa.z + wa.w * xa.w
                + wb.x * xb.x + wb.y * xb.y + wb.z * xb.z + wb.w * xb.w;
#pragma unroll
        for (int off = 16; off > 0; off >>= 1) s += __shfl_xor_sync(0xffffffffu, s, off);
        if (lane == 0)
            shP[h * 32 + d] = (den > 0.f) ? (s * rden + vb[h * 32 + d]) : 0.f;
    }
    __syncthreads();
    for (int d = 0; d < 32; d++) {
        int j = warp * 32 + d;
        const float* w = pw + j * 256;
        float4 wa = *(const float4*)(w + 4 * lane);
        float4 wb = *(const float4*)(w + 128 + 4 * lane);
        float4 xa = *(const float4*)(shP + 4 * lane);
        float4 xb = *(const float4*)(shP + 128 + 4 * lane);
        float s = wa.x * xa.x + wa.y * xa.y + wa.z * xa.z + wa.w * xa.w
                + wb.x * xb.x + wb.y * xb.y + wb.z * xb.z + wb.w * xb.w;
#pragma unroll
        for (int off = 16; off > 0; off >>= 1) s += __shfl_xor_sync(0xffffffffu, s, off);
        if (lane == 0) shO[j] = s + pb[j];
    }
    __syncthreads();
    float r = block_ln_256(shO[t], png[t], pnb[t], red);
    g_x[c * 256 + t] = (g_counts[c] > 0) ? r : 0.f;
}

// qkv projection: 4 commits per block, 128-row slice per blockIdx.y (6 slices).
__global__ void __launch_bounds__(256) k_qkv(const float* __restrict__ W,
                                             const float* __restrict__ B) {
    int cbase = blockIdx.x * 4, t = threadIdx.x, warp = t >> 5, lane = t & 31;
    int jbase = blockIdx.y * 128;
    __shared__ __align__(16) float shx[4][256];
#pragma unroll
    for (int cc = 0; cc < 4; cc++)
        shx[cc][t] = g_x[(cbase + cc) * 256 + t];
    __syncthreads();
    for (int r = 0; r < 16; r++) {
        int j = jbase + warp * 16 + r;
        const float* w = W + (size_t)j * 256;
        float4 wa = *(const float4*)(w + 4 * lane);
        float4 wb = *(const float4*)(w + 128 + 4 * lane);
        float s[4];
#pragma unroll
        for (int cc = 0; cc < 4; cc++) {
            float4 xa = *(const float4*)(&shx[cc][4 * lane]);
            float4 xb = *(const float4*)(&shx[cc][128 + 4 * lane]);
            s[cc] = wa.x * xa.x + wa.y * xa.y + wa.z * xa.z + wa.w * xa.w
                  + wb.x * xb.x + wb.y * xb.y + wb.z * xb.z + wb.w * xb.w;
        }
#pragma unroll
        for (int off = 16; off > 0; off >>= 1)
#pragma unroll
            for (int cc = 0; cc < 4; cc++)
                s[cc] += __shfl_xor_sync(0xffffffffu, s[cc], off);
        if (lane == 0) {
            float bj = B[j];
#pragma unroll
            for (int cc = 0; cc < 4; cc++)
                g_qkv[(cbase + cc) * 768 + j] = s[cc] + bj;
        }
    }
}

// attention + output projection + residual + LN1, per-commit (grid 100).
__global__ void __launch_bounds__(256) k_attn_oln(const float* __restrict__ W,
                                                  const float* __restrict__ B,
                                                  const float* __restrict__ gg,
                                                  const float* __restrict__ bb) {
    int c = blockIdx.x, t = threadIdx.x, h = t >> 5, lane = t & 31;
    __shared__ __align__(16) float shq[256];
    __shared__ float she[8][128];
    __shared__ float satt[256];
    __shared__ float sho[256];
    __shared__ float red[16];
    shq[t] = g_qkv[c * 768 + t];
    __syncthreads();
    const float scale = 0.17677669529663687f;
    float sc[4];
#pragma unroll
    for (int r = 0; r < 4; r++) {
        int m = lane + 32 * r;
        if (m < CC) {
            const float* kk = g_qkv + m * 768 + 256 + h * 32;
            const float* qq = shq + h * 32;
            float s = 0.f;
#pragma unroll
            for (int kx = 0; kx < 8; kx++) {
                float4 a = *(const float4*)(kk + 4 * kx);
                float4 b = *(const float4*)(qq + 4 * kx);
                s += a.x * b.x + a.y * b.y + a.z * b.z + a.w * b.w;
            }
            sc[r] = s * scale;
        } else sc[r] = -3.0e38f;
    }
    float M = fmaxf(fmaxf(sc[0], sc[1]), fmaxf(sc[2], sc[3]));
#pragma unroll
    for (int off = 16; off > 0; off >>= 1) M = fmaxf(M, __shfl_xor_sync(0xffffffffu, M, off));
    float sum = 0.f;
#pragma unroll
    for (int r = 0; r < 4; r++) {
        int m = lane + 32 * r;
        float e = (m < CC) ? __expf(sc[r] - M) : 0.f;
        if (m < CC) she[h][m] = e;
        sum += e;
    }
#pragma unroll
    for (int off = 16; off > 0; off >>= 1) sum += __shfl_xor_sync(0xffffffffu, sum, off);
    __syncwarp();
    float inv = 1.f / sum;
    float acc = 0.f;
#pragma unroll 4
    for (int m = 0; m < CC; m++)
        acc += she[h][m] * g_qkv[m * 768 + 512 + h * 32 + lane];
    satt[h * 32 + lane] = acc * inv;
    __syncthreads();
    for (int d = 0; d < 32; d++) {
        int j = h * 32 + d;
        const float* w = W + (size_t)j * 256;
        float4 wa = *(const float4*)(w + 4 * lane);
        float4 wb = *(const float4*)(w + 128 + 4 * lane);
        float4 xa = *(const float4*)(satt + 4 * lane);
        float4 xb = *(const float4*)(satt + 128 + 4 * lane);
        float s = wa.x * xa.x + wa.y * xa.y + wa.z * xa.z + wa.w * xa.w
                + wb.x * xb.x + wb.y * xb.y + wb.z * xb.z + wb.w * xb.w;
#pragma unroll
        for (int off = 16; off > 0; off >>= 1) s += __shfl_xor_sync(0xffffffffu, s, off);
        if (lane == 0) sho[j] = s;
    }
    __syncthreads();
    float v = g_x[c * 256 + t] + sho[t] + B[t];
    float r = block_ln_256(v, gg[t], bb[t], red);
    g_x[c * 256 + t] = r;
}

// ff1 + gelu: 4 commits per block, 128-row slice per blockIdx.y (8 slices).
__global__ void __launch_bounds__(256) k_ff1(const float* __restrict__ W,
                                             const float* __restrict__ B) {
    int cbase = blockIdx.x * 4, t = threadIdx.x, warp = t >> 5, lane = t & 31;
    int jbase = blockIdx.y * 128;
    __shared__ __align__(16) float shx[4][256];
#pragma unroll
    for (int cc = 0; cc < 4; cc++)
        shx[cc][t] = g_x[(cbase + cc) * 256 + t];
    __syncthreads();
    for (int r = 0; r < 16; r++) {
        int j = jbase + warp * 16 + r;
        const float* w = W + (size_t)j * 256;
        float4 wa = *(const float4*)(w + 4 * lane);
        float4 wb = *(const float4*)(w + 128 + 4 * lane);
        float s[4];
#pragma unroll
        for (int cc = 0; cc < 4; cc++) {
            float4 xa = *(const float4*)(&shx[cc][4 * lane]);
            float4 xb = *(const float4*)(&shx[cc][128 + 4 * lane]);
            s[cc] = wa.x * xa.x + wa.y * xa.y + wa.z * xa.z + wa.w * xa.w
                  + wb.x * xb.x + wb.y * xb.y + wb.z * xb.z + wb.w * xb.w;
        }
#pragma unroll
        for (int off = 16; off > 0; off >>= 1)
#pragma unroll
            for (int cc = 0; cc < 4; cc++)
                s[cc] += __shfl_xor_sync(0xffffffffu, s[cc], off);
        if (lane == 0) {
            float bj = B[j];
#pragma unroll
            for (int cc = 0; cc < 4; cc++)
                g_ff[(cbase + cc) * 1024 + j] = gelu_exact(s[cc] + bj);
        }
    }
}

// ff2 + residual + LN2, ONE commit per CTA (grid 100); fused head on final layer.
__global__ void __launch_bounds__(256) k_ff2(const float* __restrict__ W,
                                             const float* __restrict__ B,
                                             const float* __restrict__ gg,
                                             const float* __restrict__ bb,
                                             int final_layer,
                                             const float* __restrict__ r1w,
                                             const float* __restrict__ r1b,
                                             const float* __restrict__ r2w,
                                             const float* __restrict__ r2b,
                                             float* __restrict__ out) {
    int c = blockIdx.x, t = threadIdx.x, warp = t >> 5, lane = t & 31;
    __shared__ __align__(16) float shf[1024];
    __shared__ float sho[256];
    __shared__ float red[16];
    __shared__ __align__(16) float shx[256];
    __shared__ float shh[128];
#pragma unroll
    for (int j = 0; j < 4; j++)
        shf[t + 256 * j] = g_ff[c * 1024 + t + 256 * j];
    __syncthreads();
    for (int r = 0; r < 32; r++) {
        int j = warp * 32 + r;
        const float4* wr = (const float4*)(W + (size_t)j * 1024);
        float acc = 0.f;
#pragma unroll
        for (int q8 = 0; q8 < 8; q8++) {
            float4 wv = wr[q8 * 32 + lane];
            float4 x = *(const float4*)(&shf[q8 * 128 + 4 * lane]);
            acc += wv.x * x.x + wv.y * x.y + wv.z * x.z + wv.w * x.w;
        }
#pragma unroll
        for (int off = 16; off > 0; off >>= 1) acc += __shfl_xor_sync(0xffffffffu, acc, off);
        if (lane == 0) sho[j] = acc + B[j];
    }
    __syncthreads();
    float v = g_x[c * 256 + t] + sho[t];
    float r = block_ln_256(v, gg[t], bb[t], red);
    if (!final_layer) { g_x[c * 256 + t] = r; return; }
    shx[t] = r;
    __syncthreads();

    // ---- fused ranking head ----
    for (int rr = 0; rr < 16; rr++) {
        int j = warp * 16 + rr;
        const float* w = r1w + (size_t)j * 256;
        float4 wa = *(const float4*)(w + 4 * lane);
        float4 wb = *(const float4*)(w + 128 + 4 * lane);
        float4 xa = *(const float4*)(&shx[4 * lane]);
        float4 xb = *(const float4*)(&shx[128 + 4 * lane]);
        float s = wa.x * xa.x + wa.y * xa.y + wa.z * xa.z + wa.w * xa.w
                + wb.x * xb.x + wb.y * xb.y + wb.z * xb.z + wb.w * xb.w;
#pragma unroll
        for (int off = 16; off > 0; off >>= 1) s += __shfl_xor_sync(0xffffffffu, s, off);
        if (lane == 0) shh[j] = gelu_exact(s + r1b[j]);
    }
    __syncthreads();
    if (warp == 0) {
        float s = 0.f;
#pragma unroll
        for (int rr = 0; rr < 4; rr++)
            s += shh[lane + 32 * rr] * r2w[lane + 32 * rr];
#pragma unroll
        for (int off = 16; off > 0; off >>= 1) s += __shfl_xor_sync(0xffffffffu, s, off);
        if (lane == 0) out[c] = s + r2b[0];
    }
}

// ---------------- launch ----------------
extern "C" void kernel_launch(void* const* d_in, const int* in_sizes, int n_in,
                              void* d_out, int out_size) {
    const float* x    = (const float*)d_in[0];
    const int*   ci   = (const int*)d_in[1];
    const float* q    = (const float*)d_in[3];
    const float* kw   = (const float*)d_in[4];
    const float* vw   = (const float*)d_in[6];
    const float* vb   = (const float*)d_in[7];
    const float* pw   = (const float*)d_in[8];
    const float* pb   = (const float*)d_in[9];
    const float* png  = (const float*)d_in[10];
    const float* pnb  = (const float*)d_in[11];
    const float* tinw = (const float*)d_in[12];
    const float* tinb = (const float*)d_in[13];
    const float* totw = (const float*)d_in[14];
    const float* totb = (const float*)d_in[15];
    const float* ln1g = (const float*)d_in[16];
    const float* ln1b = (const float*)d_in[17];
    const float* ff1w = (const float*)d_in[18];
    const float* ff1b = (const float*)d_in[19];
    const float* ff2w = (const float*)d_in[20];
    const float* ff2b = (const float*)d_in[21];
    const float* ln2g = (const float*)d_in[22];
    const float* ln2b = (const float*)d_in[23];
    const float* r1w  = (const float*)d_in[24];
    const float* r1b  = (const float*)d_in[25];
    const float* r2w  = (const float*)d_in[26];
    const float* r2b  = (const float*)d_in[27];
    float* out = (float*)d_out;
    int n = in_sizes[0] / HH;

    k_wqk_init<<<9, 256>>>(q, kw);            // launch 1
    k_hist<<<256, 256>>>(ci, n);              // launch 2
    k_scatter<<<256, 256>>>(ci, n);           // launch 3
    k_main<<<dim3(CC, BY), 128>>>(x);         // launch 4  (profiled)
    k_pool<<<CC, 256>>>(vw, vb, pw, pb, png, pnb);
    for (int l = 0; l < 2; l++) {
        k_qkv<<<dim3(25, 6), 256>>>(tinw + (size_t)l * 768 * 256, tinb + l * 768);
        k_attn_oln<<<CC, 256>>>(totw + (size_t)l * 256 * 256, totb + l * 256,
                                ln1g + l * 256, ln1b + l * 256);
        k_ff1<<<dim3(25, 8), 256>>>(ff1w + (size_t)l * 1024 * 256, ff1b + l * 1024);
        k_ff2<<<CC, 256>>>(ff2w + (size_t)l * 256 * 1024, ff2b + l * 256,
                           ln2g + l * 256, ln2b + l * 256,
                           (l == 1) ? 1 : 0, r1w, r1b, r2w, r2b, out);
    }
}

// round 16
// speedup vs baseline: 1.8675x; 1.3535x over previous
#include <cuda_runtime.h>
#include <math.h>

#define HH   256
#define NHH  8
#define CC   100
#define NMAX 262144
#define BY   18           // partial chunks per commit in k_main
#define TW   8            // nodes per shared tile in k_main

typedef unsigned long long ull;

// ---------------- device scratch ----------------
__device__ __align__(16) float g_wqk[NHH * HH];
__device__ int   g_counts[CC];
__device__ int   g_offsets[CC + 1];
__device__ int   g_cursor[CC];
__device__ int   g_sorted[NMAX];
__device__ __align__(16) float g_Apart[CC * BY * NHH * HH];
__device__ float g_denpart[CC * BY * NHH];
__device__ __align__(16) float g_x[CC * HH];
__device__ __align__(16) float g_qkv[CC * 3 * HH];
__device__ __align__(16) float g_ff[CC * 4 * HH];

// ---------------- helpers ----------------
__device__ __forceinline__ ull fma2(ull a, ull b, ull c) {
    ull d;
    asm("fma.rn.f32x2 %0, %1, %2, %3;" : "=l"(d) : "l"(a), "l"(b), "l"(c));
    return d;
}
__device__ __forceinline__ void upk2(ull v, float& lo, float& hi) {
    asm("mov.b64 {%0, %1}, %2;" : "=f"(lo), "=f"(hi) : "l"(v));
}
__device__ __forceinline__ ull pk2(float lo, float hi) {
    ull r; asm("mov.b64 %0, {%1, %2};" : "=l"(r) : "f"(lo), "f"(hi)); return r;
}
__device__ __forceinline__ float gelu_exact(float v) {
    return 0.5f * v * (1.0f + erff(v * 0.70710678118654752f));
}

__device__ __forceinline__ float block_ln_256(float v, float gg, float bb, float* red) {
    int t = threadIdx.x, lane = t & 31, w = t >> 5;
    float s = v, q = v * v;
#pragma unroll
    for (int off = 16; off > 0; off >>= 1) {
        s += __shfl_xor_sync(0xffffffffu, s, off);
        q += __shfl_xor_sync(0xffffffffu, q, off);
    }
    if (lane == 0) { red[w] = s; red[8 + w] = q; }
    __syncthreads();
    float S = 0.f, Q = 0.f;
#pragma unroll
    for (int i = 0; i < 8; i++) { S += red[i]; Q += red[8 + i]; }
    float mu  = S * (1.0f / 256.0f);
    float var = Q * (1.0f / 256.0f) - mu * mu;
    return (v - mu) * rsqrtf(var + 1e-5f) * gg + bb;
}

// ---------------- setup ----------------
__global__ void k_wqk_init(const float* __restrict__ q, const float* __restrict__ kw) {
    if (blockIdx.x == 8) {
        int t = threadIdx.x;
        if (t < CC) { g_counts[t] = 0; g_cursor[t] = 0; }
        return;
    }
    const float scale = 0.17677669529663687f;
    int h = blockIdx.x, i = threadIdx.x;
    float acc = 0.f;
#pragma unroll 8
    for (int d = 0; d < 32; d++) acc += q[h * 32 + d] * kw[(h * 32 + d) * HH + i];
    g_wqk[h * HH + i] = acc * scale;
}

__global__ void __launch_bounds__(256) k_hist(const int* __restrict__ ci, int n) {
    __shared__ int sh[8][CC];
    int t = threadIdx.x, warp = t >> 5;
    for (int j = t; j < 8 * CC; j += 256) sh[j / CC][j % CC] = 0;
    __syncthreads();
    int n4 = n >> 2;
    const int4* ci4 = (const int4*)ci;
    for (int i = blockIdx.x * 256 + t; i < n4; i += gridDim.x * 256) {
        int4 v = ci4[i];
        atomicAdd(&sh[warp][v.x], 1);
        atomicAdd(&sh[warp][v.y], 1);
        atomicAdd(&sh[warp][v.z], 1);
        atomicAdd(&sh[warp][v.w], 1);
    }
    __syncthreads();
    for (int c = t; c < CC; c += 256) {
        int s = 0;
#pragma unroll
        for (int w = 0; w < 8; w++) s += sh[w][c];
        atomicAdd(&g_counts[c], s);
    }
}

__global__ void __launch_bounds__(256) k_scatter(const int* __restrict__ ci, int n) {
    __shared__ int soff[CC + 1], scnt[CC], sbase[CC], scur[CC];
    int t = threadIdx.x;
    for (int j = t; j < CC; j += 256) { scnt[j] = 0; scur[j] = 0; }
    __syncthreads();
    int per = ((n + gridDim.x - 1) / gridDim.x + 3) & ~3;
    int lo = blockIdx.x * per;
    int hi = min(n, lo + per);
    const int4* ci4 = (const int4*)ci;
    for (int i4 = (lo >> 2) + t; i4 < (hi >> 2); i4 += 256) {
        int4 v = ci4[i4];
        atomicAdd(&scnt[v.x], 1);
        atomicAdd(&scnt[v.y], 1);
        atomicAdd(&scnt[v.z], 1);
        atomicAdd(&scnt[v.w], 1);
    }
    __syncthreads();
    if (t == 0) {
        int s = 0;
        for (int c = 0; c < CC; c++) { soff[c] = s; s += g_counts[c]; }
        soff[CC] = s;
        if (blockIdx.x == 0)
            for (int c = 0; c <= CC; c++) g_offsets[c] = soff[c];
    }
    __syncthreads();
    if (t < CC) sbase[t] = soff[t] + atomicAdd(&g_cursor[t], scnt[t]);
    __syncthreads();
    for (int i = lo + t; i < hi; i += 256) {
        int c = ci[i];
        int p = sbase[c] + atomicAdd(&scur[c], 1);
        g_sorted[p] = i;
    }
}

// ---------------- main streaming pass ----------------
// CTA = 128 threads (4 warps). Warp w owns heads {2w, 2w+1}. Tiles of TW=8 rows
// double buffered in shared. Inner loop processes rows in groups of 4 so the
// 5-level SHFL butterfly runs with 8-way ILP (2 heads x 4 rows).
__global__ void __launch_bounds__(128) k_main(const float* __restrict__ X) {
    __shared__ __align__(16) float tile[2][TW * 256];   // 16KB
    int c = blockIdx.x;
    int t = threadIdx.x;
    int warp = t >> 5, lane = t & 31;
    int start = g_offsets[c], end = g_offsets[c + 1];
    int cnt = end - start;
    int chunk = (cnt + BY - 1) / BY;
    int mylo = start + blockIdx.y * chunk;
    int myhi = min(end, mylo + chunk);
    int nt = myhi - mylo;
    int ntiles = (nt + TW - 1) / TW;

    int h0 = warp * 2;
    ull w2[2][4];
#pragma unroll
    for (int hh = 0; hh < 2; hh++)
#pragma unroll
        for (int k = 0; k < 4; k++)
            w2[hh][k] = *(const ull*)(g_wqk + (h0 + hh) * 256 + k * 64 + 2 * lane);
    ull a2[2][4];
#pragma unroll
    for (int hh = 0; hh < 2; hh++)
#pragma unroll
        for (int k = 0; k < 4; k++) a2[hh][k] = 0ull;
    float dacc[2] = {0.f, 0.f};

    int lr = t >> 4, sub = t & 15;   // 16 threads per row, 8 rows

    if (nt > 0) {
        // load tile 0
        {
            int p = mylo + lr;
            int node = (p < myhi) ? g_sorted[p] : g_sorted[mylo];
            const float4* src = (const float4*)(X + (size_t)node * 256);
            float4* dst = (float4*)(&tile[0][lr * 256]);
            dst[sub]      = __ldcs(src + sub);
            dst[sub + 16] = __ldcs(src + sub + 16);
            dst[sub + 32] = __ldcs(src + sub + 32);
            dst[sub + 48] = __ldcs(src + sub + 48);
        }
        int buf = 0;
        for (int j = 0; j < ntiles; j++) {
            __syncthreads();
            if (j + 1 < ntiles) {
                int p = mylo + (j + 1) * TW + lr;
                int node = (p < myhi) ? g_sorted[p] : g_sorted[mylo];
                const float4* src = (const float4*)(X + (size_t)node * 256);
                float4* dst = (float4*)(&tile[buf ^ 1][lr * 256]);
                dst[sub]      = __ldcs(src + sub);
                dst[sub + 16] = __ldcs(src + sub + 16);
                dst[sub + 32] = __ldcs(src + sub + 32);
                dst[sub + 48] = __ldcs(src + sub + 48);
            }
            int rmax = min(TW, nt - j * TW);
            const float* tb = tile[buf];

            int rr = 0;
            // ---- groups of 4 rows: batched scores, merged butterfly ----
            for (; rr + 4 <= rmax; rr += 4) {
                ull xg[4][4];
                float p[2][4];
#pragma unroll
                for (int g = 0; g < 4; g++) {
                    const float* row = tb + (rr + g) * 256;
                    xg[g][0] = *(const ull*)(row + 2 * lane);
                    xg[g][1] = *(const ull*)(row + 64 + 2 * lane);
                    xg[g][2] = *(const ull*)(row + 128 + 2 * lane);
                    xg[g][3] = *(const ull*)(row + 192 + 2 * lane);
#pragma unroll
                    for (int hh = 0; hh < 2; hh++) {
                        ull acc = fma2(xg[g][0], w2[hh][0], 0ull);
                        acc = fma2(xg[g][1], w2[hh][1], acc);
                        acc = fma2(xg[g][2], w2[hh][2], acc);
                        acc = fma2(xg[g][3], w2[hh][3], acc);
                        float lo, hi; upk2(acc, lo, hi);
                        p[hh][g] = lo + hi;
                    }
                }
                // merged butterfly: 8 independent chains (2 heads x 4 rows)
#pragma unroll
                for (int off = 16; off > 0; off >>= 1)
#pragma unroll
                    for (int g = 0; g < 4; g++) {
                        p[0][g] += __shfl_xor_sync(0xffffffffu, p[0][g], off);
                        p[1][g] += __shfl_xor_sync(0xffffffffu, p[1][g], off);
                    }
#pragma unroll
                for (int g = 0; g < 4; g++) {
                    float e0 = __expf(p[0][g]), e1 = __expf(p[1][g]);
                    dacc[0] += e0; dacc[1] += e1;
                    ull e02 = pk2(e0, e0), e12 = pk2(e1, e1);
                    a2[0][0] = fma2(e02, xg[g][0], a2[0][0]);
                    a2[0][1] = fma2(e02, xg[g][1], a2[0][1]);
                    a2[0][2] = fma2(e02, xg[g][2], a2[0][2]);
                    a2[0][3] = fma2(e02, xg[g][3], a2[0][3]);
                    a2[1][0] = fma2(e12, xg[g][0], a2[1][0]);
                    a2[1][1] = fma2(e12, xg[g][1], a2[1][1]);
                    a2[1][2] = fma2(e12, xg[g][2], a2[1][2]);
                    a2[1][3] = fma2(e12, xg[g][3], a2[1][3]);
                }
            }
            // ---- remainder rows (<4) ----
            for (; rr < rmax; rr++) {
                const float* row = tb + rr * 256;
                ull x0 = *(const ull*)(row + 2 * lane);
                ull x1 = *(const ull*)(row + 64 + 2 * lane);
                ull x2 = *(const ull*)(row + 128 + 2 * lane);
                ull x3 = *(const ull*)(row + 192 + 2 * lane);
                float p0, p1;
                {
                    ull acc = fma2(x0, w2[0][0], 0ull);
                    acc = fma2(x1, w2[0][1], acc);
                    acc = fma2(x2, w2[0][2], acc);
                    acc = fma2(x3, w2[0][3], acc);
                    float lo, hi; upk2(acc, lo, hi); p0 = lo + hi;
                }
                {
                    ull acc = fma2(x0, w2[1][0], 0ull);
                    acc = fma2(x1, w2[1][1], acc);
                    acc = fma2(x2, w2[1][2], acc);
                    acc = fma2(x3, w2[1][3], acc);
                    float lo, hi; upk2(acc, lo, hi); p1 = lo + hi;
                }
#pragma unroll
                for (int off = 16; off > 0; off >>= 1) {
                    p0 += __shfl_xor_sync(0xffffffffu, p0, off);
                    p1 += __shfl_xor_sync(0xffffffffu, p1, off);
                }
                float e0 = __expf(p0), e1 = __expf(p1);
                dacc[0] += e0; dacc[1] += e1;
                ull e02 = pk2(e0, e0), e12 = pk2(e1, e1);
                a2[0][0] = fma2(e02, x0, a2[0][0]);
                a2[0][1] = fma2(e02, x1, a2[0][1]);
                a2[0][2] = fma2(e02, x2, a2[0][2]);
                a2[0][3] = fma2(e02, x3, a2[0][3]);
                a2[1][0] = fma2(e12, x0, a2[1][0]);
                a2[1][1] = fma2(e12, x1, a2[1][1]);
                a2[1][2] = fma2(e12, x2, a2[1][2]);
                a2[1][3] = fma2(e12, x3, a2[1][3]);
            }
            buf ^= 1;
        }
    }
    ull* base = (ull*)(g_Apart + (size_t)(c * BY + blockIdx.y) * 2048);
#pragma unroll
    for (int hh = 0; hh < 2; hh++)
#pragma unroll
        for (int k = 0; k < 4; k++)
            base[(h0 + hh) * 128 + k * 32 + lane] = a2[hh][k];
    if (lane == 0) {
        g_denpart[(c * BY + blockIdx.y) * 8 + h0]     = dacc[0];
        g_denpart[(c * BY + blockIdx.y) * 8 + h0 + 1] = dacc[1];
    }
}

// ---------------- pooling epilogue ----------------
__global__ void __launch_bounds__(256) k_pool(const float* __restrict__ vw,
                                              const float* __restrict__ vb,
                                              const float* __restrict__ pw,
                                              const float* __restrict__ pb,
                                              const float* __restrict__ png,
                                              const float* __restrict__ pnb) {
    int c = blockIdx.x, t = threadIdx.x, warp = t >> 5, lane = t & 31;
    __shared__ __align__(16) float shA[2048];
    __shared__ __align__(16) float shP[256];
    __shared__ float shO[256];
    __shared__ float shden[8];
    __shared__ float red[16];
#pragma unroll
    for (int j = 0; j < 8; j++) {
        float s = 0.f;
#pragma unroll
        for (int p = 0; p < BY; p++)
            s += g_Apart[(size_t)(c * BY + p) * 2048 + t + 256 * j];
        shA[t + 256 * j] = s;
    }
    if (t < 8) {
        float d = 0.f;
#pragma unroll
        for (int p = 0; p < BY; p++) d += g_denpart[(c * BY + p) * 8 + t];
        shden[t] = d;
    }
    __syncthreads();
    int h = warp;
    float den = shden[h];
    float rden = den > 0.f ? 1.f / den : 0.f;
    for (int d = 0; d < 32; d++) {
        const float* w = vw + (h * 32 + d) * 256;
        float4 wa = *(const float4*)(w + 4 * lane);
        float4 wb = *(const float4*)(w + 128 + 4 * lane);
        float4 xa = *(const float4*)(shA + h * 256 + 4 * lane);
        float4 xb = *(const float4*)(shA + h * 256 + 128 + 4 * lane);
        float s = wa.x * xa.x + wa.y * xa.y + wa.z * xa.z + wa.w * xa.w
                + wb.x * xb.x + wb.y * xb.y + wb.z * xb.z + wb.w * xb.w;
#pragma unroll
        for (int off = 16; off > 0; off >>= 1) s += __shfl_xor_sync(0xffffffffu, s, off);
        if (lane == 0)
            shP[h * 32 + d] = (den > 0.f) ? (s * rden + vb[h * 32 + d]) : 0.f;
    }
    __syncthreads();
    for (int d = 0; d < 32; d++) {
        int j = warp * 32 + d;
        const float* w = pw + j * 256;
        float4 wa = *(const float4*)(w + 4 * lane);
        float4 wb = *(const float4*)(w + 128 + 4 * lane);
        float4 xa = *(const float4*)(shP + 4 * lane);
        float4 xb = *(const float4*)(shP + 128 + 4 * lane);
        float s = wa.x * xa.x + wa.y * xa.y + wa.z * xa.z + wa.w * xa.w
                + wb.x * xb.x + wb.y * xb.y + wb.z * xb.z + wb.w * xb.w;
#pragma unroll
        for (int off = 16; off > 0; off >>= 1) s += __shfl_xor_sync(0xffffffffu, s, off);
        if (lane == 0) shO[j] = s + pb[j];
    }
    __syncthreads();
    float r = block_ln_256(shO[t], png[t], pnb[t], red);
    g_x[c * 256 + t] = (g_counts[c] > 0) ? r : 0.f;
}

// qkv projection: 4 commits per block, 128-row slice per blockIdx.y (6 slices).
__global__ void __launch_bounds__(256) k_qkv(const float* __restrict__ W,
                                             const float* __restrict__ B) {
    int cbase = blockIdx.x * 4, t = threadIdx.x, warp = t >> 5, lane = t & 31;
    int jbase = blockIdx.y * 128;
    __shared__ __align__(16) float shx[4][256];
#pragma unroll
    for (int cc = 0; cc < 4; cc++)
        shx[cc][t] = g_x[(cbase + cc) * 256 + t];
    __syncthreads();
    for (int r = 0; r < 16; r++) {
        int j = jbase + warp * 16 + r;
        const float* w = W + (size_t)j * 256;
        float4 wa = *(const float4*)(w + 4 * lane);
        float4 wb = *(const float4*)(w + 128 + 4 * lane);
        float s[4];
#pragma unroll
        for (int cc = 0; cc < 4; cc++) {
            float4 xa = *(const float4*)(&shx[cc][4 * lane]);
            float4 xb = *(const float4*)(&shx[cc][128 + 4 * lane]);
            s[cc] = wa.x * xa.x + wa.y * xa.y + wa.z * xa.z + wa.w * xa.w
                  + wb.x * xb.x + wb.y * xb.y + wb.z * xb.z + wb.w * xb.w;
        }
#pragma unroll
        for (int off = 16; off > 0; off >>= 1)
#pragma unroll
            for (int cc = 0; cc < 4; cc++)
                s[cc] += __shfl_xor_sync(0xffffffffu, s[cc], off);
        if (lane == 0) {
            float bj = B[j];
#pragma unroll
            for (int cc = 0; cc < 4; cc++)
                g_qkv[(cbase + cc) * 768 + j] = s[cc] + bj;
        }
    }
}

// attention + output projection + residual + LN1, per-commit (grid 100).
__global__ void __launch_bounds__(256) k_attn_oln(const float* __restrict__ W,
                                                  const float* __restrict__ B,
                                                  const float* __restrict__ gg,
                                                  const float* __restrict__ bb) {
    int c = blockIdx.x, t = threadIdx.x, h = t >> 5, lane = t & 31;
    __shared__ __align__(16) float shq[256];
    __shared__ float she[8][128];
    __shared__ float satt[256];
    __shared__ float sho[256];
    __shared__ float red[16];
    shq[t] = g_qkv[c * 768 + t];
    __syncthreads();
    const float scale = 0.17677669529663687f;
    float sc[4];
#pragma unroll
    for (int r = 0; r < 4; r++) {
        int m = lane + 32 * r;
        if (m < CC) {
            const float* kk = g_qkv + m * 768 + 256 + h * 32;
            const float* qq = shq + h * 32;
            float s = 0.f;
#pragma unroll
            for (int kx = 0; kx < 8; kx++) {
                float4 a = *(const float4*)(kk + 4 * kx);
                float4 b = *(const float4*)(qq + 4 * kx);
                s += a.x * b.x + a.y * b.y + a.z * b.z + a.w * b.w;
            }
            sc[r] = s * scale;
        } else sc[r] = -3.0e38f;
    }
    float M = fmaxf(fmaxf(sc[0], sc[1]), fmaxf(sc[2], sc[3]));
#pragma unroll
    for (int off = 16; off > 0; off >>= 1) M = fmaxf(M, __shfl_xor_sync(0xffffffffu, M, off));
    float sum = 0.f;
#pragma unroll
    for (int r = 0; r < 4; r++) {
        int m = lane + 32 * r;
        float e = (m < CC) ? __expf(sc[r] - M) : 0.f;
        if (m < CC) she[h][m] = e;
        sum += e;
    }
#pragma unroll
    for (int off = 16; off > 0; off >>= 1) sum += __shfl_xor_sync(0xffffffffu, sum, off);
    __syncwarp();
    float inv = 1.f / sum;
    float acc = 0.f;
#pragma unroll 4
    for (int m = 0; m < CC; m++)
        acc += she[h][m] * g_qkv[m * 768 + 512 + h * 32 + lane];
    satt[h * 32 + lane] = acc * inv;
    __syncthreads();
    for (int d = 0; d < 32; d++) {
        int j = h * 32 + d;
        const float* w = W + (size_t)j * 256;
        float4 wa = *(const float4*)(w + 4 * lane);
        float4 wb = *(const float4*)(w + 128 + 4 * lane);
        float4 xa = *(const float4*)(satt + 4 * lane);
        float4 xb = *(const float4*)(satt + 128 + 4 * lane);
        float s = wa.x * xa.x + wa.y * xa.y + wa.z * xa.z + wa.w * xa.w
                + wb.x * xb.x + wb.y * xb.y + wb.z * xb.z + wb.w * xb.w;
#pragma unroll
        for (int off = 16; off > 0; off >>= 1) s += __shfl_xor_sync(0xffffffffu, s, off);
        if (lane == 0) sho[j] = s;
    }
    __syncthreads();
    float v = g_x[c * 256 + t] + sho[t] + B[t];
    float r = block_ln_256(v, gg[t], bb[t], red);
    g_x[c * 256 + t] = r;
}

// ff1 + gelu: 4 commits per block, 128-row slice per blockIdx.y (8 slices).
__global__ void __launch_bounds__(256) k_ff1(const float* __restrict__ W,
                                             const float* __restrict__ B) {
    int cbase = blockIdx.x * 4, t = threadIdx.x, warp = t >> 5, lane = t & 31;
    int jbase = blockIdx.y * 128;
    __shared__ __align__(16) float shx[4][256];
#pragma unroll
    for (int cc = 0; cc < 4; cc++)
        shx[cc][t] = g_x[(cbase + cc) * 256 + t];
    __syncthreads();
    for (int r = 0; r < 16; r++) {
        int j = jbase + warp * 16 + r;
        const float* w = W + (size_t)j * 256;
        float4 wa = *(const float4*)(w + 4 * lane);
        float4 wb = *(const float4*)(w + 128 + 4 * lane);
        float s[4];
#pragma unroll
        for (int cc = 0; cc < 4; cc++) {
            float4 xa = *(const float4*)(&shx[cc][4 * lane]);
            float4 xb = *(const float4*)(&shx[cc][128 + 4 * lane]);
            s[cc] = wa.x * xa.x + wa.y * xa.y + wa.z * xa.z + wa.w * xa.w
                  + wb.x * xb.x + wb.y * xb.y + wb.z * xb.z + wb.w * xb.w;
        }
#pragma unroll
        for (int off = 16; off > 0; off >>= 1)
#pragma unroll
            for (int cc = 0; cc < 4; cc++)
                s[cc] += __shfl_xor_sync(0xffffffffu, s[cc], off);
        if (lane == 0) {
            float bj = B[j];
#pragma unroll
            for (int cc = 0; cc < 4; cc++)
                g_ff[(cbase + cc) * 1024 + j] = gelu_exact(s[cc] + bj);
        }
    }
}

// ff2 + residual + LN2, ONE commit per CTA (grid 100); fused head on final layer.
__global__ void __launch_bounds__(256) k_ff2(const float* __restrict__ W,
                                             const float* __restrict__ B,
                                             const float* __restrict__ gg,
                                             const float* __restrict__ bb,
                                             int final_layer,
                                             const float* __restrict__ r1w,
                                             const float* __restrict__ r1b,
                                             const float* __restrict__ r2w,
                                             const float* __restrict__ r2b,
                                             float* __restrict__ out) {
    int c = blockIdx.x, t = threadIdx.x, warp = t >> 5, lane = t & 31;
    __shared__ __align__(16) float shf[1024];
    __shared__ float sho[256];
    __shared__ float red[16];
    __shared__ __align__(16) float shx[256];
    __shared__ float shh[128];
#pragma unroll
    for (int j = 0; j < 4; j++)
        shf[t + 256 * j] = g_ff[c * 1024 + t + 256 * j];
    __syncthreads();
    for (int r = 0; r < 32; r++) {
        int j = warp * 32 + r;
        const float4* wr = (const float4*)(W + (size_t)j * 1024);
        float acc = 0.f;
#pragma unroll
        for (int q8 = 0; q8 < 8; q8++) {
            float4 wv = wr[q8 * 32 + lane];
            float4 x = *(const float4*)(&shf[q8 * 128 + 4 * lane]);
            acc += wv.x * x.x + wv.y * x.y + wv.z * x.z + wv.w * x.w;
        }
#pragma unroll
        for (int off = 16; off > 0; off >>= 1) acc += __shfl_xor_sync(0xffffffffu, acc, off);
        if (lane == 0) sho[j] = acc + B[j];
    }
    __syncthreads();
    float v = g_x[c * 256 + t] + sho[t];
    float r = block_ln_256(v, gg[t], bb[t], red);
    if (!final_layer) { g_x[c * 256 + t] = r; return; }
    shx[t] = r;
    __syncthreads();

    // ---- fused ranking head ----
    for (int rr = 0; rr < 16; rr++) {
        int j = warp * 16 + rr;
        const float* w = r1w + (size_t)j * 256;
        float4 wa = *(const float4*)(w + 4 * lane);
        float4 wb = *(const float4*)(w + 128 + 4 * lane);
        float4 xa = *(const float4*)(&shx[4 * lane]);
        float4 xb = *(const float4*)(&shx[128 + 4 * lane]);
        float s = wa.x * xa.x + wa.y * xa.y + wa.z * xa.z + wa.w * xa.w
                + wb.x * xb.x + wb.y * xb.y + wb.z * xb.z + wb.w * xb.w;
#pragma unroll
        for (int off = 16; off > 0; off >>= 1) s += __shfl_xor_sync(0xffffffffu, s, off);
        if (lane == 0) shh[j] = gelu_exact(s + r1b[j]);
    }
    __syncthreads();
    if (warp == 0) {
        float s = 0.f;
#pragma unroll
        for (int rr = 0; rr < 4; rr++)
            s += shh[lane + 32 * rr] * r2w[lane + 32 * rr];
#pragma unroll
        for (int off = 16; off > 0; off >>= 1) s += __shfl_xor_sync(0xffffffffu, s, off);
        if (lane == 0) out[c] = s + r2b[0];
    }
}

// ---------------- launch ----------------
extern "C" void kernel_launch(void* const* d_in, const int* in_sizes, int n_in,
                              void* d_out, int out_size) {
    const float* x    = (const float*)d_in[0];
    const int*   ci   = (const int*)d_in[1];
    const float* q    = (const float*)d_in[3];
    const float* kw   = (const float*)d_in[4];
    const float* vw   = (const float*)d_in[6];
    const float* vb   = (const float*)d_in[7];
    const float* pw   = (const float*)d_in[8];
    const float* pb   = (const float*)d_in[9];
    const float* png  = (const float*)d_in[10];
    const float* pnb  = (const float*)d_in[11];
    const float* tinw = (const float*)d_in[12];
    const float* tinb = (const float*)d_in[13];
    const float* totw = (const float*)d_in[14];
    const float* totb = (const float*)d_in[15];
    const float* ln1g = (const float*)d_in[16];
    const float* ln1b = (const float*)d_in[17];
    const float* ff1w = (const float*)d_in[18];
    const float* ff1b = (const float*)d_in[19];
    const float* ff2w = (const float*)d_in[20];
    const float* ff2b = (const float*)d_in[21];
    const float* ln2g = (const float*)d_in[22];
    const float* ln2b = (const float*)d_in[23];
    const float* r1w  = (const float*)d_in[24];
    const float* r1b  = (const float*)d_in[25];
    const float* r2w  = (const float*)d_in[26];
    const float* r2b  = (const float*)d_in[27];
    float* out = (float*)d_out;
    int n = in_sizes[0] / HH;

    k_wqk_init<<<9, 256>>>(q, kw);            // launch 1
    k_hist<<<256, 256>>>(ci, n);              // launch 2
    k_scatter<<<256, 256>>>(ci, n);           // launch 3
    k_main<<<dim3(CC, BY), 128>>>(x);         // launch 4  (profiled)
    k_pool<<<CC, 256>>>(vw, vb, pw, pb, png, pnb);
    for (int l = 0; l < 2; l++) {
        k_qkv<<<dim3(25, 6), 256>>>(tinw + (size_t)l * 768 * 256, tinb + l * 768);
        k_attn_oln<<<CC, 256>>>(totw + (size_t)l * 256 * 256, totb + l * 256,
                                ln1g + l * 256, ln1b + l * 256);
        k_ff1<<<dim3(25, 8), 256>>>(ff1w + (size_t)l * 1024 * 256, ff1b + l * 1024);
        k_ff2<<<CC, 256>>>(ff2w + (size_t)l * 256 * 1024, ff2b + l * 256,
                           ln2g + l * 256, ln2b + l * 256,
                           (l == 1) ? 1 : 0, r1w, r1b, r2w, r2b, out);
    }
}

// round 17
// speedup vs baseline: 1.8779x; 1.0055x over previous
#include <cuda_runtime.h>
#include <math.h>

#define HH   256
#define NHH  8
#define CC   100
#define NMAX 262144
#define BY   18           // partial chunks per commit in k_main
#define TW   4            // nodes per shared tile in k_main (was 8)

typedef unsigned long long ull;

// ---------------- device scratch ----------------
__device__ __align__(16) float g_wqk[NHH * HH];
__device__ int   g_counts[CC];
__device__ int   g_offsets[CC + 1];
__device__ int   g_cursor[CC];
__device__ int   g_sorted[NMAX];
__device__ __align__(16) float g_Apart[CC * BY * NHH * HH];
__device__ float g_denpart[CC * BY * NHH];
__device__ __align__(16) float g_x[CC * HH];
__device__ __align__(16) float g_qkv[CC * 3 * HH];
__device__ __align__(16) float g_ff[CC * 4 * HH];

// ---------------- helpers ----------------
__device__ __forceinline__ ull fma2(ull a, ull b, ull c) {
    ull d;
    asm("fma.rn.f32x2 %0, %1, %2, %3;" : "=l"(d) : "l"(a), "l"(b), "l"(c));
    return d;
}
__device__ __forceinline__ void upk2(ull v, float& lo, float& hi) {
    asm("mov.b64 {%0, %1}, %2;" : "=f"(lo), "=f"(hi) : "l"(v));
}
__device__ __forceinline__ ull pk2(float lo, float hi) {
    ull r; asm("mov.b64 %0, {%1, %2};" : "=l"(r) : "f"(lo), "f"(hi)); return r;
}
__device__ __forceinline__ float gelu_exact(float v) {
    return 0.5f * v * (1.0f + erff(v * 0.70710678118654752f));
}

__device__ __forceinline__ float block_ln_256(float v, float gg, float bb, float* red) {
    int t = threadIdx.x, lane = t & 31, w = t >> 5;
    float s = v, q = v * v;
#pragma unroll
    for (int off = 16; off > 0; off >>= 1) {
        s += __shfl_xor_sync(0xffffffffu, s, off);
        q += __shfl_xor_sync(0xffffffffu, q, off);
    }
    if (lane == 0) { red[w] = s; red[8 + w] = q; }
    __syncthreads();
    float S = 0.f, Q = 0.f;
#pragma unroll
    for (int i = 0; i < 8; i++) { S += red[i]; Q += red[8 + i]; }
    float mu  = S * (1.0f / 256.0f);
    float var = Q * (1.0f / 256.0f) - mu * mu;
    return (v - mu) * rsqrtf(var + 1e-5f) * gg + bb;
}

// ---------------- setup ----------------
__global__ void k_wqk_init(const float* __restrict__ q, const float* __restrict__ kw) {
    if (blockIdx.x == 8) {
        int t = threadIdx.x;
        if (t < CC) { g_counts[t] = 0; g_cursor[t] = 0; }
        return;
    }
    const float scale = 0.17677669529663687f;
    int h = blockIdx.x, i = threadIdx.x;
    float acc = 0.f;
#pragma unroll 8
    for (int d = 0; d < 32; d++) acc += q[h * 32 + d] * kw[(h * 32 + d) * HH + i];
    g_wqk[h * HH + i] = acc * scale;
}

__global__ void __launch_bounds__(256) k_hist(const int* __restrict__ ci, int n) {
    __shared__ int sh[8][CC];
    int t = threadIdx.x, warp = t >> 5;
    for (int j = t; j < 8 * CC; j += 256) sh[j / CC][j % CC] = 0;
    __syncthreads();
    int n4 = n >> 2;
    const int4* ci4 = (const int4*)ci;
    for (int i = blockIdx.x * 256 + t; i < n4; i += gridDim.x * 256) {
        int4 v = ci4[i];
        atomicAdd(&sh[warp][v.x], 1);
        atomicAdd(&sh[warp][v.y], 1);
        atomicAdd(&sh[warp][v.z], 1);
        atomicAdd(&sh[warp][v.w], 1);
    }
    __syncthreads();
    for (int c = t; c < CC; c += 256) {
        int s = 0;
#pragma unroll
        for (int w = 0; w < 8; w++) s += sh[w][c];
        atomicAdd(&g_counts[c], s);
    }
}

__global__ void __launch_bounds__(256) k_scatter(const int* __restrict__ ci, int n) {
    __shared__ int soff[CC + 1], scnt[CC], sbase[CC], scur[CC];
    int t = threadIdx.x;
    for (int j = t; j < CC; j += 256) { scnt[j] = 0; scur[j] = 0; }
    __syncthreads();
    int per = ((n + gridDim.x - 1) / gridDim.x + 3) & ~3;
    int lo = blockIdx.x * per;
    int hi = min(n, lo + per);
    const int4* ci4 = (const int4*)ci;
    for (int i4 = (lo >> 2) + t; i4 < (hi >> 2); i4 += 256) {
        int4 v = ci4[i4];
        atomicAdd(&scnt[v.x], 1);
        atomicAdd(&scnt[v.y], 1);
        atomicAdd(&scnt[v.z], 1);
        atomicAdd(&scnt[v.w], 1);
    }
    __syncthreads();
    if (t == 0) {
        int s = 0;
        for (int c = 0; c < CC; c++) { soff[c] = s; s += g_counts[c]; }
        soff[CC] = s;
        if (blockIdx.x == 0)
            for (int c = 0; c <= CC; c++) g_offsets[c] = soff[c];
    }
    __syncthreads();
    if (t < CC) sbase[t] = soff[t] + atomicAdd(&g_cursor[t], scnt[t]);
    __syncthreads();
    for (int i = lo + t; i < hi; i += 256) {
        int c = ci[i];
        int p = sbase[c] + atomicAdd(&scur[c], 1);
        g_sorted[p] = i;
    }
}

// ---------------- main streaming pass ----------------
// CTA = 128 threads (4 warps). Warp w owns heads {2w, 2w+1}. Tiles of TW=4 rows
// double buffered in shared (8.2KB smem -> ~9 CTAs/SM). Loader: 32 threads/row,
// 2 x LDG.128 each. Inner loop = one group of 4 rows, merged 8-chain butterfly.
__global__ void __launch_bounds__(128) k_main(const float* __restrict__ X) {
    __shared__ __align__(16) float tile[2][TW * 256];   // 8KB
    int c = blockIdx.x;
    int t = threadIdx.x;
    int warp = t >> 5, lane = t & 31;
    int start = g_offsets[c], end = g_offsets[c + 1];
    int cnt = end - start;
    int chunk = (cnt + BY - 1) / BY;
    int mylo = start + blockIdx.y * chunk;
    int myhi = min(end, mylo + chunk);
    int nt = myhi - mylo;
    int ntiles = (nt + TW - 1) / TW;

    int h0 = warp * 2;
    ull w2[2][4];
#pragma unroll
    for (int hh = 0; hh < 2; hh++)
#pragma unroll
        for (int k = 0; k < 4; k++)
            w2[hh][k] = *(const ull*)(g_wqk + (h0 + hh) * 256 + k * 64 + 2 * lane);
    ull a2[2][4];
#pragma unroll
    for (int hh = 0; hh < 2; hh++)
#pragma unroll
        for (int k = 0; k < 4; k++) a2[hh][k] = 0ull;
    float dacc[2] = {0.f, 0.f};

    int lr = t >> 5, sub = t & 31;   // 32 threads per row, 4 rows (1 row per warp)

    if (nt > 0) {
        // load tile 0
        {
            int p = mylo + lr;
            int node = (p < myhi) ? g_sorted[p] : g_sorted[mylo];
            const float4* src = (const float4*)(X + (size_t)node * 256);
            float4* dst = (float4*)(&tile[0][lr * 256]);
            dst[sub]      = __ldcs(src + sub);
            dst[sub + 32] = __ldcs(src + sub + 32);
        }
        int buf = 0;
        for (int j = 0; j < ntiles; j++) {
            __syncthreads();
            if (j + 1 < ntiles) {
                int p = mylo + (j + 1) * TW + lr;
                int node = (p < myhi) ? g_sorted[p] : g_sorted[mylo];
                const float4* src = (const float4*)(X + (size_t)node * 256);
                float4* dst = (float4*)(&tile[buf ^ 1][lr * 256]);
                dst[sub]      = __ldcs(src + sub);
                dst[sub + 32] = __ldcs(src + sub + 32);
            }
            int rmax = min(TW, nt - j * TW);
            const float* tb = tile[buf];

            if (rmax == 4) {
                // ---- full tile: batched scores, merged butterfly ----
                ull xg[4][4];
                float p[2][4];
#pragma unroll
                for (int g = 0; g < 4; g++) {
                    const float* row = tb + g * 256;
                    xg[g][0] = *(const ull*)(row + 2 * lane);
                    xg[g][1] = *(const ull*)(row + 64 + 2 * lane);
                    xg[g][2] = *(const ull*)(row + 128 + 2 * lane);
                    xg[g][3] = *(const ull*)(row + 192 + 2 * lane);
#pragma unroll
                    for (int hh = 0; hh < 2; hh++) {
                        ull acc = fma2(xg[g][0], w2[hh][0], 0ull);
                        acc = fma2(xg[g][1], w2[hh][1], acc);
                        acc = fma2(xg[g][2], w2[hh][2], acc);
                        acc = fma2(xg[g][3], w2[hh][3], acc);
                        float lo, hi; upk2(acc, lo, hi);
                        p[hh][g] = lo + hi;
                    }
                }
#pragma unroll
                for (int off = 16; off > 0; off >>= 1)
#pragma unroll
                    for (int g = 0; g < 4; g++) {
                        p[0][g] += __shfl_xor_sync(0xffffffffu, p[0][g], off);
                        p[1][g] += __shfl_xor_sync(0xffffffffu, p[1][g], off);
                    }
#pragma unroll
                for (int g = 0; g < 4; g++) {
                    float e0 = __expf(p[0][g]), e1 = __expf(p[1][g]);
                    dacc[0] += e0; dacc[1] += e1;
                    ull e02 = pk2(e0, e0), e12 = pk2(e1, e1);
                    a2[0][0] = fma2(e02, xg[g][0], a2[0][0]);
                    a2[0][1] = fma2(e02, xg[g][1], a2[0][1]);
                    a2[0][2] = fma2(e02, xg[g][2], a2[0][2]);
                    a2[0][3] = fma2(e02, xg[g][3], a2[0][3]);
                    a2[1][0] = fma2(e12, xg[g][0], a2[1][0]);
                    a2[1][1] = fma2(e12, xg[g][1], a2[1][1]);
                    a2[1][2] = fma2(e12, xg[g][2], a2[1][2]);
                    a2[1][3] = fma2(e12, xg[g][3], a2[1][3]);
                }
            } else {
                // ---- remainder rows ----
                for (int rr = 0; rr < rmax; rr++) {
                    const float* row = tb + rr * 256;
                    ull x0 = *(const ull*)(row + 2 * lane);
                    ull x1 = *(const ull*)(row + 64 + 2 * lane);
                    ull x2 = *(const ull*)(row + 128 + 2 * lane);
                    ull x3 = *(const ull*)(row + 192 + 2 * lane);
                    float p0, p1;
                    {
                        ull acc = fma2(x0, w2[0][0], 0ull);
                        acc = fma2(x1, w2[0][1], acc);
                        acc = fma2(x2, w2[0][2], acc);
                        acc = fma2(x3, w2[0][3], acc);
                        float lo, hi; upk2(acc, lo, hi); p0 = lo + hi;
                    }
                    {
                        ull acc = fma2(x0, w2[1][0], 0ull);
                        acc = fma2(x1, w2[1][1], acc);
                        acc = fma2(x2, w2[1][2], acc);
                        acc = fma2(x3, w2[1][3], acc);
                        float lo, hi; upk2(acc, lo, hi); p1 = lo + hi;
                    }
#pragma unroll
                    for (int off = 16; off > 0; off >>= 1) {
                        p0 += __shfl_xor_sync(0xffffffffu, p0, off);
                        p1 += __shfl_xor_sync(0xffffffffu, p1, off);
                    }
                    float e0 = __expf(p0), e1 = __expf(p1);
                    dacc[0] += e0; dacc[1] += e1;
                    ull e02 = pk2(e0, e0), e12 = pk2(e1, e1);
                    a2[0][0] = fma2(e02, x0, a2[0][0]);
                    a2[0][1] = fma2(e02, x1, a2[0][1]);
                    a2[0][2] = fma2(e02, x2, a2[0][2]);
                    a2[0][3] = fma2(e02, x3, a2[0][3]);
                    a2[1][0] = fma2(e12, x0, a2[1][0]);
                    a2[1][1] = fma2(e12, x1, a2[1][1]);
                    a2[1][2] = fma2(e12, x2, a2[1][2]);
                    a2[1][3] = fma2(e12, x3, a2[1][3]);
                }
            }
            buf ^= 1;
        }
    }
    ull* base = (ull*)(g_Apart + (size_t)(c * BY + blockIdx.y) * 2048);
#pragma unroll
    for (int hh = 0; hh < 2; hh++)
#pragma unroll
        for (int k = 0; k < 4; k++)
            base[(h0 + hh) * 128 + k * 32 + lane] = a2[hh][k];
    if (lane == 0) {
        g_denpart[(c * BY + blockIdx.y) * 8 + h0]     = dacc[0];
        g_denpart[(c * BY + blockIdx.y) * 8 + h0 + 1] = dacc[1];
    }
}

// ---------------- pooling epilogue ----------------
__global__ void __launch_bounds__(256) k_pool(const float* __restrict__ vw,
                                              const float* __restrict__ vb,
                                              const float* __restrict__ pw,
                                              const float* __restrict__ pb,
                                              const float* __restrict__ png,
                                              const float* __restrict__ pnb) {
    int c = blockIdx.x, t = threadIdx.x, warp = t >> 5, lane = t & 31;
    __shared__ __align__(16) float shA[2048];
    __shared__ __align__(16) float shP[256];
    __shared__ float shO[256];
    __shared__ float shden[8];
    __shared__ float red[16];
#pragma unroll
    for (int j = 0; j < 8; j++) {
        float s = 0.f;
#pragma unroll
        for (int p = 0; p < BY; p++)
            s += g_Apart[(size_t)(c * BY + p) * 2048 + t + 256 * j];
        shA[t + 256 * j] = s;
    }
    if (t < 8) {
        float d = 0.f;
#pragma unroll
        for (int p = 0; p < BY; p++) d += g_denpart[(c * BY + p) * 8 + t];
        shden[t] = d;
    }
    __syncthreads();
    int h = warp;
    float den = shden[h];
    float rden = den > 0.f ? 1.f / den : 0.f;
    for (int d = 0; d < 32; d++) {
        const float* w = vw + (h * 32 + d) * 256;
        float4 wa = *(const float4*)(w + 4 * lane);
        float4 wb = *(const float4*)(w + 128 + 4 * lane);
        float4 xa = *(const float4*)(shA + h * 256 + 4 * lane);
        float4 xb = *(const float4*)(shA + h * 256 + 128 + 4 * lane);
        float s = wa.x * xa.x + wa.y * xa.y + wa.z * xa.z + wa.w * xa.w
                + wb.x * xb.x + wb.y * xb.y + wb.z * xb.z + wb.w * xb.w;
#pragma unroll
        for (int off = 16; off > 0; off >>= 1) s += __shfl_xor_sync(0xffffffffu, s, off);
        if (lane == 0)
            shP[h * 32 + d] = (den > 0.f) ? (s * rden + vb[h * 32 + d]) : 0.f;
    }
    __syncthreads();
    for (int d = 0; d < 32; d++) {
        int j = warp * 32 + d;
        const float* w = pw + j * 256;
        float4 wa = *(const float4*)(w + 4 * lane);
        float4 wb = *(const float4*)(w + 128 + 4 * lane);
        float4 xa = *(const float4*)(shP + 4 * lane);
        float4 xb = *(const float4*)(shP + 128 + 4 * lane);
        float s = wa.x * xa.x + wa.y * xa.y + wa.z * xa.z + wa.w * xa.w
                + wb.x * xb.x + wb.y * xb.y + wb.z * xb.z + wb.w * xb.w;
#pragma unroll
        for (int off = 16; off > 0; off >>= 1) s += __shfl_xor_sync(0xffffffffu, s, off);
        if (lane == 0) shO[j] = s + pb[j];
    }
    __syncthreads();
    float r = block_ln_256(shO[t], png[t], pnb[t], red);
    g_x[c * 256 + t] = (g_counts[c] > 0) ? r : 0.f;
}

// qkv projection: 4 commits per block, 128-row slice per blockIdx.y (6 slices).
__global__ void __launch_bounds__(256) k_qkv(const float* __restrict__ W,
                                             const float* __restrict__ B) {
    int cbase = blockIdx.x * 4, t = threadIdx.x, warp = t >> 5, lane = t & 31;
    int jbase = blockIdx.y * 128;
    __shared__ __align__(16) float shx[4][256];
#pragma unroll
    for (int cc = 0; cc < 4; cc++)
        shx[cc][t] = g_x[(cbase + cc) * 256 + t];
    __syncthreads();
    for (int r = 0; r < 16; r++) {
        int j = jbase + warp * 16 + r;
        const float* w = W + (size_t)j * 256;
        float4 wa = *(const float4*)(w + 4 * lane);
        float4 wb = *(const float4*)(w + 128 + 4 * lane);
        float s[4];
#pragma unroll
        for (int cc = 0; cc < 4; cc++) {
            float4 xa = *(const float4*)(&shx[cc][4 * lane]);
            float4 xb = *(const float4*)(&shx[cc][128 + 4 * lane]);
            s[cc] = wa.x * xa.x + wa.y * xa.y + wa.z * xa.z + wa.w * xa.w
                  + wb.x * xb.x + wb.y * xb.y + wb.z * xb.z + wb.w * xb.w;
        }
#pragma unroll
        for (int off = 16; off > 0; off >>= 1)
#pragma unroll
            for (int cc = 0; cc < 4; cc++)
                s[cc] += __shfl_xor_sync(0xffffffffu, s[cc], off);
        if (lane == 0) {
            float bj = B[j];
#pragma unroll
            for (int cc = 0; cc < 4; cc++)
                g_qkv[(cbase + cc) * 768 + j] = s[cc] + bj;
        }
    }
}

// attention + output projection + residual + LN1, per-commit (grid 100).
__global__ void __launch_bounds__(256) k_attn_oln(const float* __restrict__ W,
                                                  const float* __restrict__ B,
                                                  const float* __restrict__ gg,
                                                  const float* __restrict__ bb) {
    int c = blockIdx.x, t = threadIdx.x, h = t >> 5, lane = t & 31;
    __shared__ __align__(16) float shq[256];
    __shared__ float she[8][128];
    __shared__ float satt[256];
    __shared__ float sho[256];
    __shared__ float red[16];
    shq[t] = g_qkv[c * 768 + t];
    __syncthreads();
    const float scale = 0.17677669529663687f;
    float sc[4];
#pragma unroll
    for (int r = 0; r < 4; r++) {
        int m = lane + 32 * r;
        if (m < CC) {
            const float* kk = g_qkv + m * 768 + 256 + h * 32;
            const float* qq = shq + h * 32;
            float s = 0.f;
#pragma unroll
            for (int kx = 0; kx < 8; kx++) {
                float4 a = *(const float4*)(kk + 4 * kx);
                float4 b = *(const float4*)(qq + 4 * kx);
                s += a.x * b.x + a.y * b.y + a.z * b.z + a.w * b.w;
            }
            sc[r] = s * scale;
        } else sc[r] = -3.0e38f;
    }
    float M = fmaxf(fmaxf(sc[0], sc[1]), fmaxf(sc[2], sc[3]));
#pragma unroll
    for (int off = 16; off > 0; off >>= 1) M = fmaxf(M, __shfl_xor_sync(0xffffffffu, M, off));
    float sum = 0.f;
#pragma unroll
    for (int r = 0; r < 4; r++) {
        int m = lane + 32 * r;
        float e = (m < CC) ? __expf(sc[r] - M) : 0.f;
        if (m < CC) she[h][m] = e;
        sum += e;
    }
#pragma unroll
    for (int off = 16; off > 0; off >>= 1) sum += __shfl_xor_sync(0xffffffffu, sum, off);
    __syncwarp();
    float inv = 1.f / sum;
    float acc = 0.f;
#pragma unroll 4
    for (int m = 0; m < CC; m++)
        acc += she[h][m] * g_qkv[m * 768 + 512 + h * 32 + lane];
    satt[h * 32 + lane] = acc * inv;
    __syncthreads();
    for (int d = 0; d < 32; d++) {
        int j = h * 32 + d;
        const float* w = W + (size_t)j * 256;
        float4 wa = *(const float4*)(w + 4 * lane);
        float4 wb = *(const float4*)(w + 128 + 4 * lane);
        float4 xa = *(const float4*)(satt + 4 * lane);
        float4 xb = *(const float4*)(satt + 128 + 4 * lane);
        float s = wa.x * xa.x + wa.y * xa.y + wa.z * xa.z + wa.w * xa.w
                + wb.x * xb.x + wb.y * xb.y + wb.z * xb.z + wb.w * xb.w;
#pragma unroll
        for (int off = 16; off > 0; off >>= 1) s += __shfl_xor_sync(0xffffffffu, s, off);
        if (lane == 0) sho[j] = s;
    }
    __syncthreads();
    float v = g_x[c * 256 + t] + sho[t] + B[t];
    float r = block_ln_256(v, gg[t], bb[t], red);
    g_x[c * 256 + t] = r;
}

// ff1 + gelu: 4 commits per block, 128-row slice per blockIdx.y (8 slices).
__global__ void __launch_bounds__(256) k_ff1(const float* __restrict__ W,
                                             const float* __restrict__ B) {
    int cbase = blockIdx.x * 4, t = threadIdx.x, warp = t >> 5, lane = t & 31;
    int jbase = blockIdx.y * 128;
    __shared__ __align__(16) float shx[4][256];
#pragma unroll
    for (int cc = 0; cc < 4; cc++)
        shx[cc][t] = g_x[(cbase + cc) * 256 + t];
    __syncthreads();
    for (int r = 0; r < 16; r++) {
        int j = jbase + warp * 16 + r;
        const float* w = W + (size_t)j * 256;
        float4 wa = *(const float4*)(w + 4 * lane);
        float4 wb = *(const float4*)(w + 128 + 4 * lane);
        float s[4];
#pragma unroll
        for (int cc = 0; cc < 4; cc++) {
            float4 xa = *(const float4*)(&shx[cc][4 * lane]);
            float4 xb = *(const float4*)(&shx[cc][128 + 4 * lane]);
            s[cc] = wa.x * xa.x + wa.y * xa.y + wa.z * xa.z + wa.w * xa.w
                  + wb.x * xb.x + wb.y * xb.y + wb.z * xb.z + wb.w * xb.w;
        }
#pragma unroll
        for (int off = 16; off > 0; off >>= 1)
#pragma unroll
            for (int cc = 0; cc < 4; cc++)
                s[cc] += __shfl_xor_sync(0xffffffffu, s[cc], off);
        if (lane == 0) {
            float bj = B[j];
#pragma unroll
            for (int cc = 0; cc < 4; cc++)
                g_ff[(cbase + cc) * 1024 + j] = gelu_exact(s[cc] + bj);
        }
    }
}

// ff2 + residual + LN2, ONE commit per CTA (grid 100); fused head on final layer.
__global__ void __launch_bounds__(256) k_ff2(const float* __restrict__ W,
                                             const float* __restrict__ B,
                                             const float* __restrict__ gg,
                                             const float* __restrict__ bb,
                                             int final_layer,
                                             const float* __restrict__ r1w,
                                             const float* __restrict__ r1b,
                                             const float* __restrict__ r2w,
                                             const float* __restrict__ r2b,
                                             float* __restrict__ out) {
    int c = blockIdx.x, t = threadIdx.x, warp = t >> 5, lane = t & 31;
    __shared__ __align__(16) float shf[1024];
    __shared__ float sho[256];
    __shared__ float red[16];
    __shared__ __align__(16) float shx[256];
    __shared__ float shh[128];
#pragma unroll
    for (int j = 0; j < 4; j++)
        shf[t + 256 * j] = g_ff[c * 1024 + t + 256 * j];
    __syncthreads();
    for (int r = 0; r < 32; r++) {
        int j = warp * 32 + r;
        const float4* wr = (const float4*)(W + (size_t)j * 1024);
        float acc = 0.f;
#pragma unroll
        for (int q8 = 0; q8 < 8; q8++) {
            float4 wv = wr[q8 * 32 + lane];
            float4 x = *(const float4*)(&shf[q8 * 128 + 4 * lane]);
            acc += wv.x * x.x + wv.y * x.y + wv.z * x.z + wv.w * x.w;
        }
#pragma unroll
        for (int off = 16; off > 0; off >>= 1) acc += __shfl_xor_sync(0xffffffffu, acc, off);
        if (lane == 0) sho[j] = acc + B[j];
    }
    __syncthreads();
    float v = g_x[c * 256 + t] + sho[t];
    float r = block_ln_256(v, gg[t], bb[t], red);
    if (!final_layer) { g_x[c * 256 + t] = r; return; }
    shx[t] = r;
    __syncthreads();

    // ---- fused ranking head ----
    for (int rr = 0; rr < 16; rr++) {
        int j = warp * 16 + rr;
        const float* w = r1w + (size_t)j * 256;
        float4 wa = *(const float4*)(w + 4 * lane);
        float4 wb = *(const float4*)(w + 128 + 4 * lane);
        float4 xa = *(const float4*)(&shx[4 * lane]);
        float4 xb = *(const float4*)(&shx[128 + 4 * lane]);
        float s = wa.x * xa.x + wa.y * xa.y + wa.z * xa.z + wa.w * xa.w
                + wb.x * xb.x + wb.y * xb.y + wb.z * xb.z + wb.w * xb.w;
#pragma unroll
        for (int off = 16; off > 0; off >>= 1) s += __shfl_xor_sync(0xffffffffu, s, off);
        if (lane == 0) shh[j] = gelu_exact(s + r1b[j]);
    }
    __syncthreads();
    if (warp == 0) {
        float s = 0.f;
#pragma unroll
        for (int rr = 0; rr < 4; rr++)
            s += shh[lane + 32 * rr] * r2w[lane + 32 * rr];
#pragma unroll
        for (int off = 16; off > 0; off >>= 1) s += __shfl_xor_sync(0xffffffffu, s, off);
        if (lane == 0) out[c] = s + r2b[0];
    }
}

// ---------------- launch ----------------
extern "C" void kernel_launch(void* const* d_in, const int* in_sizes, int n_in,
                              void* d_out, int out_size) {
    const float* x    = (const float*)d_in[0];
    const int*   ci   = (const int*)d_in[1];
    const float* q    = (const float*)d_in[3];
    const float* kw   = (const float*)d_in[4];
    const float* vw   = (const float*)d_in[6];
    const float* vb   = (const float*)d_in[7];
    const float* pw   = (const float*)d_in[8];
    const float* pb   = (const float*)d_in[9];
    const float* png  = (const float*)d_in[10];
    const float* pnb  = (const float*)d_in[11];
    const float* tinw = (const float*)d_in[12];
    const float* tinb = (const float*)d_in[13];
    const float* totw = (const float*)d_in[14];
    const float* totb = (const float*)d_in[15];
    const float* ln1g = (const float*)d_in[16];
    const float* ln1b = (const float*)d_in[17];
    const float* ff1w = (const float*)d_in[18];
    const float* ff1b = (const float*)d_in[19];
    const float* ff2w = (const float*)d_in[20];
    const float* ff2b = (const float*)d_in[21];
    const float* ln2g = (const float*)d_in[22];
    const float* ln2b = (const float*)d_in[23];
    const float* r1w  = (const float*)d_in[24];
    const float* r1b  = (const float*)d_in[25];
    const float* r2w  = (const float*)d_in[26];
    const float* r2b  = (const float*)d_in[27];
    float* out = (float*)d_out;
    int n = in_sizes[0] / HH;

    k_wqk_init<<<9, 256>>>(q, kw);            // launch 1
    k_hist<<<256, 256>>>(ci, n);              // launch 2
    k_scatter<<<256, 256>>>(ci, n);           // launch 3
    k_main<<<dim3(CC, BY), 128>>>(x);         // launch 4  (profiled)
    k_pool<<<CC, 256>>>(vw, vb, pw, pb, png, pnb);
    for (int l = 0; l < 2; l++) {
        k_qkv<<<dim3(25, 6), 256>>>(tinw + (size_t)l * 768 * 256, tinb + l * 768);
        k_attn_oln<<<CC, 256>>>(totw + (size_t)l * 256 * 256, totb + l * 256,
                                ln1g + l * 256, ln1b + l * 256);
        k_ff1<<<dim3(25, 8), 256>>>(ff1w + (size_t)l * 1024 * 256, ff1b + l * 1024);
        k_ff2<<<CC, 256>>>(ff2w + (size_t)l * 256 * 1024, ff2b + l * 256,
                           ln2g + l * 256, ln2b + l * 256,
                           (l == 1) ? 1 : 0, r1w, r1b, r2w, r2b, out);
    }
}